// round 1
// baseline (speedup 1.0000x reference)
#include <cuda_runtime.h>
#include <math.h>

#define Bn   8
#define SEQ  1024
#define DM   512
#define HID  256
#define NH   8
#define DH   64
#define MROWS (Bn*SEQ)

// ---------------- scratch (device globals; no allocation) ----------------
__device__ float g_Q [MROWS*DM];
__device__ float g_K [MROWS*DM];
__device__ float g_VV[MROWS*DM];
__device__ float g_VC[MROWS*DM];
__device__ float g_H [MROWS*HID];
__device__ float g_VD[MROWS*DM];
__device__ float g_AO[MROWS*DM];
__device__ float g_CW[Bn*DM];

// ---------------- channel gate: prof = mean_n(value); cw = sig(relu(prof@Wc1+bc1)@Wc2+bc2)
__global__ void channel_gate_kernel(const float* __restrict__ value,
                                    const float* __restrict__ Wc1, const float* __restrict__ bc1,
                                    const float* __restrict__ Wc2, const float* __restrict__ bc2,
                                    float* __restrict__ cw)
{
    int b = blockIdx.x;          // 8 blocks
    int t = threadIdx.x;         // 256 threads
    __shared__ float prof[DM];
    __shared__ float hid[HID];

    const float* vb = value + (size_t)b * SEQ * DM;
    for (int d = t; d < DM; d += 256) {
        float s = 0.f;
        #pragma unroll 8
        for (int n = 0; n < SEQ; n++) s += vb[(size_t)n * DM + d];
        prof[d] = s * (1.0f / SEQ);
    }
    __syncthreads();
    {
        float s = bc1[t];
        #pragma unroll 8
        for (int d = 0; d < DM; d++) s += prof[d] * Wc1[d * HID + t];
        hid[t] = fmaxf(s, 0.f);
    }
    __syncthreads();
    for (int d = t; d < DM; d += 256) {
        float s = bc2[d];
        #pragma unroll 8
        for (int h = 0; h < HID; h++) s += hid[h] * Wc2[h * DM + d];
        cw[b * DM + d] = 1.f / (1.f + __expf(-s));
    }
}

// ---------------- GEMM: C[M,N] = epilogue(A[M,K] @ W[K,N] + bias)
// MODE 0: plain
// MODE 1: A scaled per-element by scaleA[batch(row)*DM + k]   (channel-gated V proj)
// MODE 2: relu
// MODE 3: C = E1 * sigmoid(acc + bias) + E2                   (v_dual assembly)
#define KS 32
template<int MODE>
__global__ __launch_bounds__(256)
void gemm128(const float* __restrict__ A, const float* __restrict__ W,
             const float* __restrict__ bias, float* __restrict__ C,
             int M, int Kd, int Nd,
             const float* __restrict__ scaleA,
             const float* __restrict__ E1, const float* __restrict__ E2)
{
    __shared__ float As[KS][128];
    __shared__ float Bs[KS][128];

    int t  = threadIdx.x;
    int tx = t & 15;     // 0..15 -> 8 cols each
    int ty = t >> 4;     // 0..15 -> 8 rows each
    int m0 = blockIdx.y * 128;
    int n0 = blockIdx.x * 128;
    int bb = m0 >> 10;   // batch index (128-row tile never crosses a 1024-row batch)

    float acc[8][8];
    #pragma unroll
    for (int i = 0; i < 8; i++)
        #pragma unroll
        for (int j = 0; j < 8; j++) acc[i][j] = 0.f;

    for (int k0 = 0; k0 < Kd; k0 += KS) {
        // A tile -> As[kk][row_local] (transposed store)
        #pragma unroll
        for (int f = t; f < 128 * (KS / 4); f += 256) {
            int rl  = f >> 3;          // KS/4 = 8 float4 per row
            int kk4 = (f & 7) << 2;
            float4 v = *(const float4*)&A[(size_t)(m0 + rl) * Kd + k0 + kk4];
            if (MODE == 1) {
                const float* s = scaleA + bb * DM + k0 + kk4;
                v.x *= s[0]; v.y *= s[1]; v.z *= s[2]; v.w *= s[3];
            }
            As[kk4 + 0][rl] = v.x;
            As[kk4 + 1][rl] = v.y;
            As[kk4 + 2][rl] = v.z;
            As[kk4 + 3][rl] = v.w;
        }
        // W tile -> Bs[kk][col]
        #pragma unroll
        for (int f = t; f < KS * 32; f += 256) {
            int kk = f >> 5;
            int c4 = (f & 31) << 2;
            *(float4*)&Bs[kk][c4] = *(const float4*)&W[(size_t)(k0 + kk) * Nd + n0 + c4];
        }
        __syncthreads();

        #pragma unroll 8
        for (int kk = 0; kk < KS; kk++) {
            float a[8], bv[8];
            *(float4*)&a[0]  = *(const float4*)&As[kk][ty * 8];
            *(float4*)&a[4]  = *(const float4*)&As[kk][ty * 8 + 4];
            *(float4*)&bv[0] = *(const float4*)&Bs[kk][tx * 8];
            *(float4*)&bv[4] = *(const float4*)&Bs[kk][tx * 8 + 4];
            #pragma unroll
            for (int i = 0; i < 8; i++)
                #pragma unroll
                for (int j = 0; j < 8; j++) acc[i][j] += a[i] * bv[j];
        }
        __syncthreads();
    }

    // epilogue
    #pragma unroll
    for (int i = 0; i < 8; i++) {
        int r = m0 + ty * 8 + i;
        float out[8];
        #pragma unroll
        for (int j = 0; j < 8; j++) {
            int c = n0 + tx * 8 + j;
            float x = acc[i][j] + bias[c];
            if (MODE == 2) x = fmaxf(x, 0.f);
            if (MODE == 3) {
                float sw = 1.f / (1.f + __expf(-x));
                size_t idx = (size_t)r * Nd + c;
                x = E1[idx] * sw + E2[idx];
            }
            out[j] = x;
        }
        *(float4*)&C[(size_t)r * Nd + n0 + tx * 8]     = *(float4*)&out[0];
        *(float4*)&C[(size_t)r * Nd + n0 + tx * 8 + 4] = *(float4*)&out[4];
    }
}

// ---------------- flash attention: one thread owns one query row (no cross-thread softmax)
__global__ __launch_bounds__(128)
void attn_kernel(const float* __restrict__ Q, const float* __restrict__ Kp,
                 const float* __restrict__ V, float* __restrict__ O)
{
    int qt = blockIdx.x;   // 8 query tiles of 128
    int h  = blockIdx.y;   // 8 heads
    int b  = blockIdx.z;   // 8 batches
    int t  = threadIdx.x;  // 128 threads = 128 query rows
    int row = qt * 128 + t;

    __shared__ float Ks[32][64];
    __shared__ float Vs[32][64];
    __shared__ float S[128][33];   // padded: conflict-free per-thread score scratch

    const float scale = 0.125f;    // 1/sqrt(64)

    float q[64];
    {
        const float4* qp = (const float4*)(Q + (size_t)(b * SEQ + row) * DM + h * DH);
        #pragma unroll
        for (int u = 0; u < 16; u++) {
            float4 v = qp[u];
            q[4*u] = v.x; q[4*u+1] = v.y; q[4*u+2] = v.z; q[4*u+3] = v.w;
        }
    }
    float o[64];
    #pragma unroll
    for (int d = 0; d < 64; d++) o[d] = 0.f;
    float m = -1e30f, l = 0.f;

    for (int kt = 0; kt < SEQ / 32; kt++) {
        #pragma unroll
        for (int w = 0; w < 4; w++) {
            int i4 = t + w * 128;
            int kr = i4 >> 4;
            int c4 = (i4 & 15) << 2;
            size_t gidx = (size_t)(b * SEQ + kt * 32 + kr) * DM + h * DH + c4;
            *(float4*)&Ks[kr][c4] = *(const float4*)&Kp[gidx];
            *(float4*)&Vs[kr][c4] = *(const float4*)&V[gidx];
        }
        __syncthreads();

        float tmax = -1e30f;
        #pragma unroll 4
        for (int j = 0; j < 32; j++) {
            float s = 0.f;
            #pragma unroll
            for (int d4 = 0; d4 < 16; d4++) {
                float4 kv = *(const float4*)&Ks[j][d4 * 4];
                s += q[4*d4] * kv.x + q[4*d4+1] * kv.y + q[4*d4+2] * kv.z + q[4*d4+3] * kv.w;
            }
            s *= scale;
            S[t][j] = s;
            tmax = fmaxf(tmax, s);
        }

        float mn = fmaxf(m, tmax);
        float c  = __expf(m - mn);
        m = mn;
        l *= c;
        #pragma unroll
        for (int d = 0; d < 64; d++) o[d] *= c;

        #pragma unroll 4
        for (int j = 0; j < 32; j++) {
            float p = __expf(S[t][j] - mn);
            l += p;
            #pragma unroll
            for (int d4 = 0; d4 < 16; d4++) {
                float4 vv = *(const float4*)&Vs[j][d4 * 4];
                o[4*d4]   += p * vv.x;
                o[4*d4+1] += p * vv.y;
                o[4*d4+2] += p * vv.z;
                o[4*d4+3] += p * vv.w;
            }
        }
        __syncthreads();
    }

    float inv = 1.f / l;
    float* op = O + (size_t)(b * SEQ + row) * DM + h * DH;
    #pragma unroll
    for (int u = 0; u < 16; u++) {
        float4 v;
        v.x = o[4*u] * inv; v.y = o[4*u+1] * inv; v.z = o[4*u+2] * inv; v.w = o[4*u+3] * inv;
        *(float4*)&op[u * 4] = v;
    }
}

// ---------------- launch ----------------
extern "C" void kernel_launch(void* const* d_in, const int* in_sizes, int n_in,
                              void* d_out, int out_size)
{
    const float* query  = (const float*)d_in[0];
    const float* key_in = (const float*)d_in[1];
    const float* value  = (const float*)d_in[2];
    const float* Wq  = (const float*)d_in[3];
    const float* bq  = (const float*)d_in[4];
    const float* Wk  = (const float*)d_in[5];
    const float* bk  = (const float*)d_in[6];
    const float* Wv  = (const float*)d_in[7];
    const float* bv  = (const float*)d_in[8];
    const float* Wo  = (const float*)d_in[9];
    const float* bo  = (const float*)d_in[10];
    const float* Ws1 = (const float*)d_in[11];
    const float* bs1 = (const float*)d_in[12];
    const float* Ws2 = (const float*)d_in[13];
    const float* bs2 = (const float*)d_in[14];
    const float* Wc1 = (const float*)d_in[15];
    const float* bc1 = (const float*)d_in[16];
    const float* Wc2 = (const float*)d_in[17];
    const float* bc2 = (const float*)d_in[18];

    float *pQ, *pK, *pVV, *pVC, *pH, *pVD, *pAO, *pCW;
    cudaGetSymbolAddress((void**)&pQ,  g_Q);
    cudaGetSymbolAddress((void**)&pK,  g_K);
    cudaGetSymbolAddress((void**)&pVV, g_VV);
    cudaGetSymbolAddress((void**)&pVC, g_VC);
    cudaGetSymbolAddress((void**)&pH,  g_H);
    cudaGetSymbolAddress((void**)&pVD, g_VD);
    cudaGetSymbolAddress((void**)&pAO, g_AO);
    cudaGetSymbolAddress((void**)&pCW, g_CW);

    // 1) channel gate weights cw[b,d]
    channel_gate_kernel<<<Bn, 256>>>(value, Wc1, bc1, Wc2, bc2, pCW);

    dim3 g512(DM / 128, MROWS / 128);   // (4, 64)
    dim3 g256(HID / 128, MROWS / 128);  // (2, 64)

    // 2) projections
    gemm128<0><<<g512, 256>>>(query,  Wq, bq, pQ,  MROWS, DM, DM, nullptr, nullptr, nullptr);
    gemm128<0><<<g512, 256>>>(key_in, Wk, bk, pK,  MROWS, DM, DM, nullptr, nullptr, nullptr);
    gemm128<0><<<g512, 256>>>(value,  Wv, bv, pVV, MROWS, DM, DM, nullptr, nullptr, nullptr);
    gemm128<1><<<g512, 256>>>(value,  Wv, bv, pVC, MROWS, DM, DM, pCW,     nullptr, nullptr);

    // 3) spatial gate hidden = relu(VV @ Ws1 + bs1)
    gemm128<2><<<g256, 256>>>(pVV, Ws1, bs1, pH, MROWS, DM, HID, nullptr, nullptr, nullptr);

    // 4) v_dual = VV * sigmoid(H @ Ws2 + bs2) + VC
    gemm128<3><<<g512, 256>>>(pH, Ws2, bs2, pVD, MROWS, HID, DM, nullptr, pVV, pVC);

    // 5) attention
    attn_kernel<<<dim3(SEQ / 128, NH, Bn), 128>>>(pQ, pK, pVD, pAO);

    // 6) output projection
    gemm128<0><<<g512, 256>>>(pAO, Wo, bo, (float*)d_out, MROWS, DM, DM, nullptr, nullptr, nullptr);
}

// round 3
// speedup vs baseline: 2.3187x; 2.3187x over previous
#include <cuda_runtime.h>
#include <math.h>
#include <cstdint>

#define Bn   8
#define SEQ  1024
#define DM   512
#define HID  256
#define NH   8
#define DH   64
#define MROWS (Bn*SEQ)

// ---------------- scratch (device globals; no allocation) ----------------
__device__ float g_Q [MROWS*DM];
__device__ float g_K [MROWS*DM];
__device__ float g_VV[MROWS*DM];
__device__ float g_VC[MROWS*DM];
__device__ float g_H [MROWS*HID];
__device__ float g_VD[MROWS*DM];
__device__ float g_AO[MROWS*DM];
__device__ float g_CW[Bn*DM];
__device__ float g_WT[4*DM*DM + 2*DM*HID];

#define WT_Q  0
#define WT_K  (DM*DM)
#define WT_V  (2*DM*DM)
#define WT_O  (3*DM*DM)
#define WT_S1 (4*DM*DM)
#define WT_S2 (4*DM*DM + DM*HID)

// ---------------- helpers ----------------
__device__ __forceinline__ uint32_t f2tf(float x) {
    uint32_t u; asm("cvt.rna.tf32.f32 %0, %1;" : "=r"(u) : "f"(x)); return u;
}
__device__ __forceinline__ void mma_tf32(float* c, const uint32_t* a, uint32_t b0, uint32_t b1) {
    asm volatile("mma.sync.aligned.m16n8k8.row.col.f32.tf32.tf32.f32 "
        "{%0,%1,%2,%3}, {%4,%5,%6,%7}, {%8,%9}, {%0,%1,%2,%3};"
        : "+f"(c[0]), "+f"(c[1]), "+f"(c[2]), "+f"(c[3])
        : "r"(a[0]), "r"(a[1]), "r"(a[2]), "r"(a[3]), "r"(b0), "r"(b1));
}

// ---------------- weight transpose ----------------
__global__ void transpose_kernel(const float* __restrict__ in, float* __restrict__ out,
                                 int R, int C)
{
    __shared__ float tile[32][33];
    int bx = blockIdx.x * 32, by = blockIdx.y * 32;
    int tx = threadIdx.x, ty = threadIdx.y;
    #pragma unroll
    for (int i = 0; i < 32; i += 8)
        tile[ty + i][tx] = in[(size_t)(by + ty + i) * C + bx + tx];
    __syncthreads();
    #pragma unroll
    for (int i = 0; i < 32; i += 8)
        out[(size_t)(bx + ty + i) * R + by + tx] = tile[tx][ty + i];
}

// ---------------- channel gate ----------------
__global__ void channel_gate_kernel(const float* __restrict__ value,
                                    const float* __restrict__ Wc1, const float* __restrict__ bc1,
                                    const float* __restrict__ Wc2, const float* __restrict__ bc2,
                                    float* __restrict__ cw)
{
    int b = blockIdx.x;
    int t = threadIdx.x;
    __shared__ float prof[DM];
    __shared__ float hid[HID];

    const float* vb = value + (size_t)b * SEQ * DM;
    for (int d = t; d < DM; d += 256) {
        float s = 0.f;
        #pragma unroll 8
        for (int n = 0; n < SEQ; n++) s += vb[(size_t)n * DM + d];
        prof[d] = s * (1.0f / SEQ);
    }
    __syncthreads();
    {
        float s = bc1[t];
        #pragma unroll 8
        for (int d = 0; d < DM; d++) s += prof[d] * Wc1[d * HID + t];
        hid[t] = fmaxf(s, 0.f);
    }
    __syncthreads();
    for (int d = t; d < DM; d += 256) {
        float s = bc2[d];
        #pragma unroll 8
        for (int h = 0; h < HID; h++) s += hid[h] * Wc2[h * DM + d];
        cw[b * DM + d] = 1.f / (1.f + __expf(-s));
    }
}

// ---------------- tf32 mma GEMM: C[M,N] = epi(A[M,K] @ WT[N,K]^T + bias)
// MODE 0: plain   MODE 1: A scaled by cw[batch,k]
// MODE 2: relu    MODE 3: C = E1 * sigmoid(acc+bias) + E2
// smem word layout: A pad 36/row (128 rows); B pad 136/k-row (32 rows) + XOR(4q) swizzle
#define APITCH 36
#define BPITCH 136
#define AWORDS (128*APITCH)   // 4608
#define BWORDS (32*BPITCH)    // 4352
#define SMEM_GEMM ((2*AWORDS + 2*BWORDS)*4)  // 71680 B

template<int MODE>
__global__ __launch_bounds__(256)
void tgemm(const float* __restrict__ A, const float* __restrict__ WT,
           const float* __restrict__ bias, float* __restrict__ C,
           int Kd, int Nd,
           const float* __restrict__ scaleA,
           const float* __restrict__ E1, const float* __restrict__ E2)
{
    extern __shared__ uint32_t usm[];
    const int t    = threadIdx.x;
    const int lane = t & 31;
    const int wid  = t >> 5;
    const int g    = lane >> 2;
    const int tg   = lane & 3;
    const int wm   = wid & 3;       // 4 warps over M (32 rows each)
    const int wn   = wid >> 2;      // 2 warps over N (64 cols each)
    const int m0   = blockIdx.y * 128;
    const int n0   = blockIdx.x * 128;
    const int bb   = blockIdx.y >> 3;   // batch index
    const int NK   = Kd / 32;

    float acc[2][8][4];
    #pragma unroll
    for (int mt = 0; mt < 2; mt++)
        #pragma unroll
        for (int nt = 0; nt < 8; nt++)
            #pragma unroll
            for (int j = 0; j < 4; j++) acc[mt][nt][j] = 0.f;

    // ---- producer pieces ----
    float4 ra[4], rb[4];
    auto ldg_chunk = [&](int kc) {
        const int k0 = kc * 32;
        #pragma unroll
        for (int i = 0; i < 4; i++) {
            int idx = t + i * 256;
            int row = idx >> 3, q = idx & 7;
            ra[i] = *(const float4*)&A[(size_t)(m0 + row) * Kd + k0 + q * 4];
            if (MODE == 1) {
                float4 s4 = *(const float4*)&scaleA[bb * DM + k0 + q * 4];
                ra[i].x *= s4.x; ra[i].y *= s4.y; ra[i].z *= s4.z; ra[i].w *= s4.w;
            }
            rb[i] = *(const float4*)&WT[(size_t)(n0 + row) * Kd + k0 + q * 4];
        }
    };
    auto sts_chunk = [&](int buf) {
        uint32_t* Aw = usm + (buf ? AWORDS : 0);
        uint32_t* Bw = usm + 2 * AWORDS + (buf ? BWORDS : 0);
        #pragma unroll
        for (int i = 0; i < 4; i++) {
            int idx = t + i * 256;
            int row = idx >> 3, q = idx & 7;
            uint4 u; u.x = f2tf(ra[i].x); u.y = f2tf(ra[i].y);
                     u.z = f2tf(ra[i].z); u.w = f2tf(ra[i].w);
            *(uint4*)&Aw[row * APITCH + q * 4] = u;
            int sw = 4 * q;   // XOR swizzle: 4*((k>>2)&7), k=4q+j
            Bw[(4 * q + 0) * BPITCH + (row ^ sw)] = f2tf(rb[i].x);
            Bw[(4 * q + 1) * BPITCH + (row ^ sw)] = f2tf(rb[i].y);
            Bw[(4 * q + 2) * BPITCH + (row ^ sw)] = f2tf(rb[i].z);
            Bw[(4 * q + 3) * BPITCH + (row ^ sw)] = f2tf(rb[i].w);
        }
    };
    auto compute = [&](int buf) {
        const uint32_t* Aw = usm + (buf ? AWORDS : 0);
        const uint32_t* Bw = usm + 2 * AWORDS + (buf ? BWORDS : 0);
        #pragma unroll
        for (int ks = 0; ks < 4; ks++) {
            uint32_t af[2][4];
            #pragma unroll
            for (int mt = 0; mt < 2; mt++) {
                int r0 = wm * 32 + mt * 16 + g;
                int c0 = ks * 8 + tg;
                af[mt][0] = Aw[r0 * APITCH + c0];
                af[mt][1] = Aw[(r0 + 8) * APITCH + c0];
                af[mt][2] = Aw[r0 * APITCH + c0 + 4];
                af[mt][3] = Aw[(r0 + 8) * APITCH + c0 + 4];
            }
            #pragma unroll
            for (int nt = 0; nt < 8; nt++) {
                int kl = ks * 8 + tg;
                int nn = wn * 64 + nt * 8 + g;
                uint32_t b0 = Bw[kl * BPITCH + (nn ^ (4 * ((kl >> 2) & 7)))];
                uint32_t b1 = Bw[(kl + 4) * BPITCH + (nn ^ (4 * (((kl + 4) >> 2) & 7)))];
                mma_tf32(acc[0][nt], af[0], b0, b1);
                mma_tf32(acc[1][nt], af[1], b0, b1);
            }
        }
    };

    ldg_chunk(0);
    sts_chunk(0);
    __syncthreads();

    for (int kc = 0; kc < NK; kc++) {
        if (kc + 1 < NK) ldg_chunk(kc + 1);
        compute(kc & 1);
        if (kc + 1 < NK) sts_chunk((kc + 1) & 1);
        __syncthreads();
    }

    // ---- epilogue ----
    #pragma unroll
    for (int mt = 0; mt < 2; mt++) {
        int r_lo = m0 + wm * 32 + mt * 16 + g;
        int r_hi = r_lo + 8;
        #pragma unroll
        for (int nt = 0; nt < 8; nt++) {
            int col = n0 + wn * 64 + nt * 8 + 2 * tg;
            float bx = bias[col], by = bias[col + 1];
            float v0 = acc[mt][nt][0] + bx;
            float v1 = acc[mt][nt][1] + by;
            float v2 = acc[mt][nt][2] + bx;
            float v3 = acc[mt][nt][3] + by;
            if (MODE == 2) {
                v0 = fmaxf(v0, 0.f); v1 = fmaxf(v1, 0.f);
                v2 = fmaxf(v2, 0.f); v3 = fmaxf(v3, 0.f);
            }
            if (MODE == 3) {
                size_t i_lo = (size_t)r_lo * Nd + col;
                size_t i_hi = (size_t)r_hi * Nd + col;
                float2 e1l = *(const float2*)&E1[i_lo];
                float2 e2l = *(const float2*)&E2[i_lo];
                float2 e1h = *(const float2*)&E1[i_hi];
                float2 e2h = *(const float2*)&E2[i_hi];
                v0 = e1l.x / (1.f + __expf(-v0)) + e2l.x;
                v1 = e1l.y / (1.f + __expf(-v1)) + e2l.y;
                v2 = e1h.x / (1.f + __expf(-v2)) + e2h.x;
                v3 = e1h.y / (1.f + __expf(-v3)) + e2h.y;
            }
            *(float2*)&C[(size_t)r_lo * Nd + col] = make_float2(v0, v1);
            *(float2*)&C[(size_t)r_hi * Nd + col] = make_float2(v2, v3);
        }
    }
}

// ---------------- flash attention with tf32 mma ----------------
// block: 128 q-rows, 8 warps (m16 each); key chunks of 128
#define KVPITCH 72
#define SMEM_ATTN (2*128*KVPITCH*4)   // 73728 B

__global__ __launch_bounds__(256)
void attn_kernel(const float* __restrict__ Q, const float* __restrict__ Kp,
                 const float* __restrict__ V, float* __restrict__ O)
{
    extern __shared__ uint32_t usm[];
    uint32_t* Ks = usm;
    uint32_t* Vs = usm + 128 * KVPITCH;

    const int qt = blockIdx.x;
    const int h  = blockIdx.y;
    const int b  = blockIdx.z;
    const int t  = threadIdx.x;
    const int lane = t & 31;
    const int wid  = t >> 5;
    const int g  = lane >> 2;
    const int tg = lane & 3;
    const int q0 = qt * 128 + wid * 16;

    // Q fragments, pre-scaled by 1/sqrt(64)
    uint32_t aq[8][4];
    {
        const float* Qb = Q + ((size_t)(b * SEQ + q0)) * DM + h * DH;
        #pragma unroll
        for (int ks = 0; ks < 8; ks++) {
            int c0 = ks * 8 + tg;
            aq[ks][0] = f2tf(0.125f * Qb[(size_t)g * DM + c0]);
            aq[ks][1] = f2tf(0.125f * Qb[(size_t)(g + 8) * DM + c0]);
            aq[ks][2] = f2tf(0.125f * Qb[(size_t)g * DM + c0 + 4]);
            aq[ks][3] = f2tf(0.125f * Qb[(size_t)(g + 8) * DM + c0 + 4]);
        }
    }

    float o[8][4];
    #pragma unroll
    for (int nt = 0; nt < 8; nt++)
        #pragma unroll
        for (int j = 0; j < 4; j++) o[nt][j] = 0.f;
    float m_lo = -1e30f, m_hi = -1e30f, l_lo = 0.f, l_hi = 0.f;

    const int src  = (lane & ~3) | (tg >> 1);
    const int src2 = src + 2;
    const bool odd = (lane & 1);

    for (int kt = 0; kt < SEQ / 128; kt++) {
        // ---- load K,V chunk (coalesced), tf32-convert, swizzled store ----
        #pragma unroll
        for (int i = 0; i < 8; i++) {
            int idx = t + i * 256;
            int tok = idx >> 4, qd = idx & 15;
            size_t gaddr = ((size_t)(b * SEQ + kt * 128 + tok)) * DM + h * DH + qd * 4;
            float4 kv = *(const float4*)&Kp[gaddr];
            float4 vv = *(const float4*)&V[gaddr];
            uint4 uk; uk.x = f2tf(kv.x); uk.y = f2tf(kv.y); uk.z = f2tf(kv.z); uk.w = f2tf(kv.w);
            uint4 uv; uv.x = f2tf(vv.x); uv.y = f2tf(vv.y); uv.z = f2tf(vv.z); uv.w = f2tf(vv.w);
            int sw = ((tok >> 2) & 1) << 2;
            *(uint4*)&Ks[tok * KVPITCH + ((qd * 4) ^ sw)] = uk;
            *(uint4*)&Vs[tok * KVPITCH + qd * 4] = uv;
        }
        __syncthreads();

        // ---- S = Q @ K^T ----
        float s[16][4];
        #pragma unroll
        for (int nt = 0; nt < 16; nt++)
            #pragma unroll
            for (int j = 0; j < 4; j++) s[nt][j] = 0.f;
        #pragma unroll
        for (int ks = 0; ks < 8; ks++) {
            #pragma unroll
            for (int nt = 0; nt < 16; nt++) {
                int key = nt * 8 + g;
                int d0 = ks * 8 + tg;
                int sw = ((key >> 2) & 1) << 2;
                uint32_t b0 = Ks[key * KVPITCH + (d0 ^ sw)];
                uint32_t b1 = Ks[key * KVPITCH + ((d0 + 4) ^ sw)];
                mma_tf32(s[nt], aq[ks], b0, b1);
            }
        }

        // ---- online softmax ----
        float tl = -1e30f, th = -1e30f;
        #pragma unroll
        for (int nt = 0; nt < 16; nt++) {
            tl = fmaxf(tl, fmaxf(s[nt][0], s[nt][1]));
            th = fmaxf(th, fmaxf(s[nt][2], s[nt][3]));
        }
        tl = fmaxf(tl, __shfl_xor_sync(0xffffffffu, tl, 1));
        tl = fmaxf(tl, __shfl_xor_sync(0xffffffffu, tl, 2));
        th = fmaxf(th, __shfl_xor_sync(0xffffffffu, th, 1));
        th = fmaxf(th, __shfl_xor_sync(0xffffffffu, th, 2));
        float mn_l = fmaxf(m_lo, tl), mn_h = fmaxf(m_hi, th);
        float fl = __expf(m_lo - mn_l), fh = __expf(m_hi - mn_h);
        m_lo = mn_l; m_hi = mn_h;

        float sl = 0.f, sh = 0.f;
        #pragma unroll
        for (int nt = 0; nt < 16; nt++) {
            s[nt][0] = __expf(s[nt][0] - m_lo);
            s[nt][1] = __expf(s[nt][1] - m_lo);
            s[nt][2] = __expf(s[nt][2] - m_hi);
            s[nt][3] = __expf(s[nt][3] - m_hi);
            sl += s[nt][0] + s[nt][1];
            sh += s[nt][2] + s[nt][3];
        }
        sl += __shfl_xor_sync(0xffffffffu, sl, 1);
        sl += __shfl_xor_sync(0xffffffffu, sl, 2);
        sh += __shfl_xor_sync(0xffffffffu, sh, 1);
        sh += __shfl_xor_sync(0xffffffffu, sh, 2);
        l_lo = l_lo * fl + sl;
        l_hi = l_hi * fh + sh;
        #pragma unroll
        for (int nt = 0; nt < 8; nt++) {
            o[nt][0] *= fl; o[nt][1] *= fl;
            o[nt][2] *= fh; o[nt][3] *= fh;
        }

        // ---- O += P @ V : repack P accum -> A frags via shuffles ----
        #pragma unroll
        for (int kk = 0; kk < 16; kk++) {
            float t0 = __shfl_sync(0xffffffffu, s[kk][0], src);
            float t1 = __shfl_sync(0xffffffffu, s[kk][1], src);
            float t2 = __shfl_sync(0xffffffffu, s[kk][2], src);
            float t3 = __shfl_sync(0xffffffffu, s[kk][3], src);
            float u0 = __shfl_sync(0xffffffffu, s[kk][0], src2);
            float u1 = __shfl_sync(0xffffffffu, s[kk][1], src2);
            float u2 = __shfl_sync(0xffffffffu, s[kk][2], src2);
            float u3 = __shfl_sync(0xffffffffu, s[kk][3], src2);
            uint32_t pa[4];
            pa[0] = f2tf(odd ? t1 : t0);
            pa[1] = f2tf(odd ? t3 : t2);
            pa[2] = f2tf(odd ? u1 : u0);
            pa[3] = f2tf(odd ? u3 : u2);
            #pragma unroll
            for (int nt = 0; nt < 8; nt++) {
                int krow = kk * 8 + tg;
                int dd = nt * 8 + g;
                uint32_t b0 = Vs[krow * KVPITCH + dd];
                uint32_t b1 = Vs[(krow + 4) * KVPITCH + dd];
                mma_tf32(o[nt], pa, b0, b1);
            }
        }
        __syncthreads();
    }

    // ---- normalize + write ----
    float inv_lo = 1.f / l_lo, inv_hi = 1.f / l_hi;
    #pragma unroll
    for (int nt = 0; nt < 8; nt++) {
        int col = h * DH + nt * 8 + 2 * tg;
        size_t r_lo = (size_t)(b * SEQ + q0 + g) * DM + col;
        size_t r_hi = (size_t)(b * SEQ + q0 + g + 8) * DM + col;
        *(float2*)&O[r_lo] = make_float2(o[nt][0] * inv_lo, o[nt][1] * inv_lo);
        *(float2*)&O[r_hi] = make_float2(o[nt][2] * inv_hi, o[nt][3] * inv_hi);
    }
}

// ---------------- launch ----------------
extern "C" void kernel_launch(void* const* d_in, const int* in_sizes, int n_in,
                              void* d_out, int out_size)
{
    const float* query  = (const float*)d_in[0];
    const float* key_in = (const float*)d_in[1];
    const float* value  = (const float*)d_in[2];
    const float* Wq  = (const float*)d_in[3];
    const float* bq  = (const float*)d_in[4];
    const float* Wk  = (const float*)d_in[5];
    const float* bk  = (const float*)d_in[6];
    const float* Wv  = (const float*)d_in[7];
    const float* bv  = (const float*)d_in[8];
    const float* Wo  = (const float*)d_in[9];
    const float* bo  = (const float*)d_in[10];
    const float* Ws1 = (const float*)d_in[11];
    const float* bs1 = (const float*)d_in[12];
    const float* Ws2 = (const float*)d_in[13];
    const float* bs2 = (const float*)d_in[14];
    const float* Wc1 = (const float*)d_in[15];
    const float* bc1 = (const float*)d_in[16];
    const float* Wc2 = (const float*)d_in[17];
    const float* bc2 = (const float*)d_in[18];

    float *pQ, *pK, *pVV, *pVC, *pH, *pVD, *pAO, *pCW, *pWT;
    cudaGetSymbolAddress((void**)&pQ,  g_Q);
    cudaGetSymbolAddress((void**)&pK,  g_K);
    cudaGetSymbolAddress((void**)&pVV, g_VV);
    cudaGetSymbolAddress((void**)&pVC, g_VC);
    cudaGetSymbolAddress((void**)&pH,  g_H);
    cudaGetSymbolAddress((void**)&pVD, g_VD);
    cudaGetSymbolAddress((void**)&pAO, g_AO);
    cudaGetSymbolAddress((void**)&pCW, g_CW);
    cudaGetSymbolAddress((void**)&pWT, g_WT);

    cudaFuncSetAttribute(tgemm<0>, cudaFuncAttributeMaxDynamicSharedMemorySize, SMEM_GEMM);
    cudaFuncSetAttribute(tgemm<1>, cudaFuncAttributeMaxDynamicSharedMemorySize, SMEM_GEMM);
    cudaFuncSetAttribute(tgemm<2>, cudaFuncAttributeMaxDynamicSharedMemorySize, SMEM_GEMM);
    cudaFuncSetAttribute(tgemm<3>, cudaFuncAttributeMaxDynamicSharedMemorySize, SMEM_GEMM);
    cudaFuncSetAttribute(attn_kernel, cudaFuncAttributeMaxDynamicSharedMemorySize, SMEM_ATTN);

    // 0) transpose weights -> [N, K]
    transpose_kernel<<<dim3(16, 16), dim3(32, 8)>>>(Wq,  pWT + WT_Q,  DM, DM);
    transpose_kernel<<<dim3(16, 16), dim3(32, 8)>>>(Wk,  pWT + WT_K,  DM, DM);
    transpose_kernel<<<dim3(16, 16), dim3(32, 8)>>>(Wv,  pWT + WT_V,  DM, DM);
    transpose_kernel<<<dim3(16, 16), dim3(32, 8)>>>(Wo,  pWT + WT_O,  DM, DM);
    transpose_kernel<<<dim3(8,  16), dim3(32, 8)>>>(Ws1, pWT + WT_S1, DM, HID);
    transpose_kernel<<<dim3(16,  8), dim3(32, 8)>>>(Ws2, pWT + WT_S2, HID, DM);

    // 1) channel gate weights cw[b,d]
    channel_gate_kernel<<<Bn, 256>>>(value, Wc1, bc1, Wc2, bc2, pCW);

    dim3 g512(DM / 128, MROWS / 128);   // (4, 64)
    dim3 g256(HID / 128, MROWS / 128);  // (2, 64)

    // 2) projections
    tgemm<0><<<g512, 256, SMEM_GEMM>>>(query,  pWT + WT_Q, bq, pQ,  DM, DM, nullptr, nullptr, nullptr);
    tgemm<0><<<g512, 256, SMEM_GEMM>>>(key_in, pWT + WT_K, bk, pK,  DM, DM, nullptr, nullptr, nullptr);
    tgemm<0><<<g512, 256, SMEM_GEMM>>>(value,  pWT + WT_V, bv, pVV, DM, DM, nullptr, nullptr, nullptr);
    tgemm<1><<<g512, 256, SMEM_GEMM>>>(value,  pWT + WT_V, bv, pVC, DM, DM, pCW,     nullptr, nullptr);

    // 3) spatial gate hidden = relu(VV @ Ws1 + bs1)
    tgemm<2><<<g256, 256, SMEM_GEMM>>>(pVV, pWT + WT_S1, bs1, pH, DM, HID, nullptr, nullptr, nullptr);

    // 4) v_dual = VV * sigmoid(H @ Ws2 + bs2) + VC
    tgemm<3><<<g512, 256, SMEM_GEMM>>>(pH, pWT + WT_S2, bs2, pVD, HID, DM, nullptr, pVV, pVC);

    // 5) attention
    attn_kernel<<<dim3(SEQ / 128, NH, Bn), 256, SMEM_ATTN>>>(pQ, pK, pVD, pAO);

    // 6) output projection
    tgemm<0><<<g512, 256, SMEM_GEMM>>>(pAO, pWT + WT_O, bo, (float*)d_out, DM, DM, nullptr, nullptr, nullptr);
}

// round 4
// speedup vs baseline: 3.1997x; 1.3800x over previous
#include <cuda_runtime.h>
#include <math.h>
#include <cstdint>

#define Bn   8
#define SEQ  1024
#define DM   512
#define HID  256
#define NH   8
#define DH   64
#define MROWS (Bn*SEQ)

// ---------------- scratch (device globals; no allocation) ----------------
__device__ float g_Q [MROWS*DM];
__device__ float g_K [MROWS*DM];
__device__ float g_VV[MROWS*DM];
__device__ float g_VC[MROWS*DM];
__device__ float g_H [MROWS*HID];
__device__ float g_VD[MROWS*DM];
__device__ float g_AO[MROWS*DM];
__device__ float g_CW[Bn*DM];
__device__ float g_PART[Bn*8*DM];
__device__ float g_WT[4*DM*DM + 2*DM*HID];

#define WT_Q  0
#define WT_K  (DM*DM)
#define WT_V  (2*DM*DM)
#define WT_O  (3*DM*DM)
#define WT_S1 (4*DM*DM)
#define WT_S2 (4*DM*DM + DM*HID)

// ---------------- helpers ----------------
__device__ __forceinline__ uint32_t f2tf(float x) {
    uint32_t u; asm("cvt.rna.tf32.f32 %0, %1;" : "=r"(u) : "f"(x)); return u;
}
__device__ __forceinline__ void mma_tf32(float* c, const uint32_t* a, uint32_t b0, uint32_t b1) {
    asm volatile("mma.sync.aligned.m16n8k8.row.col.f32.tf32.tf32.f32 "
        "{%0,%1,%2,%3}, {%4,%5,%6,%7}, {%8,%9}, {%0,%1,%2,%3};"
        : "+f"(c[0]), "+f"(c[1]), "+f"(c[2]), "+f"(c[3])
        : "r"(a[0]), "r"(a[1]), "r"(a[2]), "r"(a[3]), "r"(b0), "r"(b1));
}

// ---------------- prep: all weight transposes + tf32 pre-convert, ONE launch
// out[C][R] = tf32(in[R][C]^T)
__global__ void prep_weights(const float* __restrict__ Wq, const float* __restrict__ Wk,
                             const float* __restrict__ Wv, const float* __restrict__ Wo,
                             const float* __restrict__ Ws1, const float* __restrict__ Ws2,
                             float* __restrict__ WT)
{
    int bid = blockIdx.x;           // 1280 blocks total
    const float* in; float* out; int R, C, tb;
    if      (bid < 256)  { in = Wq;  out = WT + WT_Q;  R = DM; C = DM;  tb = bid; }
    else if (bid < 512)  { in = Wk;  out = WT + WT_K;  R = DM; C = DM;  tb = bid - 256; }
    else if (bid < 768)  { in = Wv;  out = WT + WT_V;  R = DM; C = DM;  tb = bid - 512; }
    else if (bid < 1024) { in = Wo;  out = WT + WT_O;  R = DM; C = DM;  tb = bid - 768; }
    else if (bid < 1152) { in = Ws1; out = WT + WT_S1; R = DM; C = HID; tb = bid - 1024; }
    else                 { in = Ws2; out = WT + WT_S2; R = HID; C = DM; tb = bid - 1152; }
    int tilesX = C >> 5;
    int bx = (tb % tilesX) * 32, by = (tb / tilesX) * 32;

    __shared__ float tile[32][33];
    int tx = threadIdx.x, ty = threadIdx.y;      // (32, 8)
    #pragma unroll
    for (int i = 0; i < 32; i += 8)
        tile[ty + i][tx] = in[(size_t)(by + ty + i) * C + bx + tx];
    __syncthreads();
    #pragma unroll
    for (int i = 0; i < 32; i += 8)
        out[(size_t)(bx + ty + i) * R + by + tx] = __uint_as_float(f2tf(tile[tx][ty + i]));
}

// ---------------- mean: partial sums over 128-seq slices (full-chip BW)
__global__ void mean_part_kernel(const float* __restrict__ value, float* __restrict__ part)
{
    int b = blockIdx.y, s = blockIdx.x;          // (8, 8)
    int t = threadIdx.x;                         // 256
    const float* vb = value + ((size_t)b * SEQ + s * 128) * DM;
    #pragma unroll
    for (int d = t; d < DM; d += 256) {
        float acc = 0.f;
        #pragma unroll 8
        for (int n = 0; n < 128; n++) acc += vb[(size_t)n * DM + d];
        part[(b * 8 + s) * DM + d] = acc;
    }
}

// ---------------- channel gate MLP (reads partials only)
__global__ void gate_kernel(const float* __restrict__ part,
                            const float* __restrict__ Wc1, const float* __restrict__ bc1,
                            const float* __restrict__ Wc2, const float* __restrict__ bc2,
                            float* __restrict__ cw)
{
    int b = blockIdx.x;
    int t = threadIdx.x;         // 256
    __shared__ float prof[DM];
    __shared__ float hid[HID];
    for (int d = t; d < DM; d += 256) {
        float s = 0.f;
        #pragma unroll
        for (int k = 0; k < 8; k++) s += part[(b * 8 + k) * DM + d];
        prof[d] = s * (1.0f / SEQ);
    }
    __syncthreads();
    {
        float s = bc1[t];
        #pragma unroll 8
        for (int d = 0; d < DM; d++) s += prof[d] * Wc1[d * HID + t];
        hid[t] = fmaxf(s, 0.f);
    }
    __syncthreads();
    for (int d = t; d < DM; d += 256) {
        float s = bc2[d];
        #pragma unroll 8
        for (int h = 0; h < HID; h++) s += hid[h] * Wc2[h * DM + d];
        cw[b * DM + d] = 1.f / (1.f + __expf(-s));
    }
}

// ---------------- tf32 mma GEMM body: C[M,N] = epi(A[M,K] @ WT[N,K]^T + bias)
// A cvt'd at producer; WT already tf32 bits (raw copy).
// MODE 0: plain   MODE 1: A scaled by cw[batch,k]
// MODE 2: relu    MODE 3: C = E1 * sigmoid(acc+bias) + E2
#define PITCH 36
#define TW (128*PITCH)                 // 4608 words per tile
#define SMEM_GEMM (4*TW*4)             // 73728 B (2 stages x (A,B))

template<int MODE>
__device__ __forceinline__
void gemm_body(const float* __restrict__ A, const float* __restrict__ B,
               const float* __restrict__ bias, float* __restrict__ C,
               int Kd, int Nd,
               const float* __restrict__ scaleA,
               const float* __restrict__ E1, const float* __restrict__ E2,
               int m0, int n0, int bb)
{
    extern __shared__ uint32_t usm[];
    const int t    = threadIdx.x;
    const int lane = t & 31;
    const int wid  = t >> 5;
    const int g    = lane >> 2;
    const int tg   = lane & 3;
    const int wm   = wid & 3;
    const int wn   = wid >> 2;
    const int NK   = Kd / 32;

    float acc[2][8][4];
    #pragma unroll
    for (int mt = 0; mt < 2; mt++)
        #pragma unroll
        for (int nt = 0; nt < 8; nt++)
            #pragma unroll
            for (int j = 0; j < 4; j++) acc[mt][nt][j] = 0.f;

    float4 ra[4], rb[4];
    auto ldg_chunk = [&](int kc) {
        const int k0 = kc * 32;
        #pragma unroll
        for (int i = 0; i < 4; i++) {
            int idx = t + i * 256;
            int row = idx >> 3, q = idx & 7;
            ra[i] = *(const float4*)&A[(size_t)(m0 + row) * Kd + k0 + q * 4];
            if (MODE == 1) {
                float4 s4 = *(const float4*)&scaleA[bb * DM + k0 + q * 4];
                ra[i].x *= s4.x; ra[i].y *= s4.y; ra[i].z *= s4.z; ra[i].w *= s4.w;
            }
            rb[i] = *(const float4*)&B[(size_t)(n0 + row) * Kd + k0 + q * 4];
        }
    };
    auto sts_chunk = [&](int buf) {
        uint32_t* Aw = usm + buf * 2 * TW;
        uint32_t* Bw = Aw + TW;
        #pragma unroll
        for (int i = 0; i < 4; i++) {
            int idx = t + i * 256;
            int row = idx >> 3, q = idx & 7;
            uint4 ua; ua.x = f2tf(ra[i].x); ua.y = f2tf(ra[i].y);
                      ua.z = f2tf(ra[i].z); ua.w = f2tf(ra[i].w);
            *(uint4*)&Aw[row * PITCH + q * 4] = ua;
            *(uint4*)&Bw[row * PITCH + q * 4] = *(uint4*)&rb[i];
        }
    };
    auto compute = [&](int buf) {
        const uint32_t* Aw = usm + buf * 2 * TW;
        const uint32_t* Bw = Aw + TW;
        #pragma unroll
        for (int ks = 0; ks < 4; ks++) {
            const int c0 = ks * 8 + tg;
            uint32_t af[2][4];
            #pragma unroll
            for (int mt = 0; mt < 2; mt++) {
                int r0 = wm * 32 + mt * 16 + g;
                af[mt][0] = Aw[r0 * PITCH + c0];
                af[mt][1] = Aw[(r0 + 8) * PITCH + c0];
                af[mt][2] = Aw[r0 * PITCH + c0 + 4];
                af[mt][3] = Aw[(r0 + 8) * PITCH + c0 + 4];
            }
            #pragma unroll
            for (int nt = 0; nt < 8; nt++) {
                int nn = wn * 64 + nt * 8 + g;
                uint32_t b0 = Bw[nn * PITCH + c0];
                uint32_t b1 = Bw[nn * PITCH + c0 + 4];
                mma_tf32(acc[0][nt], af[0], b0, b1);
                mma_tf32(acc[1][nt], af[1], b0, b1);
            }
        }
    };

    ldg_chunk(0);
    sts_chunk(0);
    __syncthreads();

    for (int kc = 0; kc < NK; kc++) {
        if (kc + 1 < NK) ldg_chunk(kc + 1);
        compute(kc & 1);
        if (kc + 1 < NK) sts_chunk((kc + 1) & 1);
        __syncthreads();
    }

    #pragma unroll
    for (int mt = 0; mt < 2; mt++) {
        int r_lo = m0 + wm * 32 + mt * 16 + g;
        int r_hi = r_lo + 8;
        #pragma unroll
        for (int nt = 0; nt < 8; nt++) {
            int col = n0 + wn * 64 + nt * 8 + 2 * tg;
            float bx = bias[col], by = bias[col + 1];
            float v0 = acc[mt][nt][0] + bx;
            float v1 = acc[mt][nt][1] + by;
            float v2 = acc[mt][nt][2] + bx;
            float v3 = acc[mt][nt][3] + by;
            if (MODE == 2) {
                v0 = fmaxf(v0, 0.f); v1 = fmaxf(v1, 0.f);
                v2 = fmaxf(v2, 0.f); v3 = fmaxf(v3, 0.f);
            }
            if (MODE == 3) {
                size_t i_lo = (size_t)r_lo * Nd + col;
                size_t i_hi = (size_t)r_hi * Nd + col;
                float2 e1l = *(const float2*)&E1[i_lo];
                float2 e2l = *(const float2*)&E2[i_lo];
                float2 e1h = *(const float2*)&E1[i_hi];
                float2 e2h = *(const float2*)&E2[i_hi];
                v0 = e1l.x / (1.f + __expf(-v0)) + e2l.x;
                v1 = e1l.y / (1.f + __expf(-v1)) + e2l.y;
                v2 = e1h.x / (1.f + __expf(-v2)) + e2h.x;
                v3 = e1h.y / (1.f + __expf(-v3)) + e2h.y;
            }
            *(float2*)&C[(size_t)r_lo * Nd + col] = make_float2(v0, v1);
            *(float2*)&C[(size_t)r_hi * Nd + col] = make_float2(v2, v3);
        }
    }
}

template<int MODE>
__global__ __launch_bounds__(256)
void tgemm(const float* __restrict__ A, const float* __restrict__ B,
           const float* __restrict__ bias, float* __restrict__ C,
           int Kd, int Nd,
           const float* __restrict__ scaleA,
           const float* __restrict__ E1, const float* __restrict__ E2)
{
    gemm_body<MODE>(A, B, bias, C, Kd, Nd, scaleA, E1, E2,
                    blockIdx.y * 128, blockIdx.x * 128, blockIdx.y >> 3);
}

// merged Q/K/VV/VC projections: blockIdx.z selects the GEMM
__global__ __launch_bounds__(256)
void proj4(const float* __restrict__ query, const float* __restrict__ key_in,
           const float* __restrict__ value, const float* __restrict__ WTb,
           const float* __restrict__ bq, const float* __restrict__ bk,
           const float* __restrict__ bv, const float* __restrict__ cw,
           float* __restrict__ oQ, float* __restrict__ oK,
           float* __restrict__ oVV, float* __restrict__ oVC)
{
    const int z = blockIdx.z;
    const int m0 = blockIdx.y * 128, n0 = blockIdx.x * 128, bb = blockIdx.y >> 3;
    if (z == 0)
        gemm_body<0>(query,  WTb + WT_Q, bq, oQ,  DM, DM, nullptr, nullptr, nullptr, m0, n0, bb);
    else if (z == 1)
        gemm_body<0>(key_in, WTb + WT_K, bk, oK,  DM, DM, nullptr, nullptr, nullptr, m0, n0, bb);
    else if (z == 2)
        gemm_body<0>(value,  WTb + WT_V, bv, oVV, DM, DM, nullptr, nullptr, nullptr, m0, n0, bb);
    else
        gemm_body<1>(value,  WTb + WT_V, bv, oVC, DM, DM, cw,      nullptr, nullptr, m0, n0, bb);
}

// ---------------- flash attention (tf32 mma, 64-token KV chunks, single wave)
#define KVPITCH 72
#define KVTOK   64
#define SMEM_ATTN (2*KVTOK*KVPITCH*4)   // 36864 B

__global__ __launch_bounds__(256)
void attn_kernel(const float* __restrict__ Q, const float* __restrict__ Kp,
                 const float* __restrict__ V, float* __restrict__ O)
{
    extern __shared__ uint32_t usm[];
    uint32_t* Ks = usm;
    uint32_t* Vs = usm + KVTOK * KVPITCH;

    const int qt = blockIdx.x;
    const int h  = blockIdx.y;
    const int b  = blockIdx.z;
    const int t  = threadIdx.x;
    const int lane = t & 31;
    const int wid  = t >> 5;
    const int g  = lane >> 2;
    const int tg = lane & 3;
    const int q0 = qt * 128 + wid * 16;

    uint32_t aq[8][4];
    {
        const float* Qb = Q + ((size_t)(b * SEQ + q0)) * DM + h * DH;
        #pragma unroll
        for (int ks = 0; ks < 8; ks++) {
            int c0 = ks * 8 + tg;
            aq[ks][0] = f2tf(0.125f * Qb[(size_t)g * DM + c0]);
            aq[ks][1] = f2tf(0.125f * Qb[(size_t)(g + 8) * DM + c0]);
            aq[ks][2] = f2tf(0.125f * Qb[(size_t)g * DM + c0 + 4]);
            aq[ks][3] = f2tf(0.125f * Qb[(size_t)(g + 8) * DM + c0 + 4]);
        }
    }

    float o[8][4];
    #pragma unroll
    for (int nt = 0; nt < 8; nt++)
        #pragma unroll
        for (int j = 0; j < 4; j++) o[nt][j] = 0.f;
    float m_lo = -1e30f, m_hi = -1e30f, l_lo = 0.f, l_hi = 0.f;

    const int src  = (lane & ~3) | (tg >> 1);
    const int src2 = src + 2;
    const bool odd = (lane & 1);

    for (int kt = 0; kt < SEQ / KVTOK; kt++) {
        #pragma unroll
        for (int i = 0; i < 4; i++) {
            int idx = t + i * 256;
            int tok = idx >> 4, qd = idx & 15;
            size_t gaddr = ((size_t)(b * SEQ + kt * KVTOK + tok)) * DM + h * DH + qd * 4;
            float4 kv = *(const float4*)&Kp[gaddr];
            float4 vv = *(const float4*)&V[gaddr];
            uint4 uk; uk.x = f2tf(kv.x); uk.y = f2tf(kv.y); uk.z = f2tf(kv.z); uk.w = f2tf(kv.w);
            uint4 uv; uv.x = f2tf(vv.x); uv.y = f2tf(vv.y); uv.z = f2tf(vv.z); uv.w = f2tf(vv.w);
            int sw = ((tok >> 2) & 1) << 2;
            *(uint4*)&Ks[tok * KVPITCH + ((qd * 4) ^ sw)] = uk;
            *(uint4*)&Vs[tok * KVPITCH + qd * 4] = uv;
        }
        __syncthreads();

        float s[8][4];
        #pragma unroll
        for (int nt = 0; nt < 8; nt++)
            #pragma unroll
            for (int j = 0; j < 4; j++) s[nt][j] = 0.f;
        #pragma unroll
        for (int ks = 0; ks < 8; ks++) {
            #pragma unroll
            for (int nt = 0; nt < 8; nt++) {
                int key = nt * 8 + g;
                int d0 = ks * 8 + tg;
                int sw = ((key >> 2) & 1) << 2;
                uint32_t b0 = Ks[key * KVPITCH + (d0 ^ sw)];
                uint32_t b1 = Ks[key * KVPITCH + ((d0 + 4) ^ sw)];
                mma_tf32(s[nt], aq[ks], b0, b1);
            }
        }

        float tl = -1e30f, th = -1e30f;
        #pragma unroll
        for (int nt = 0; nt < 8; nt++) {
            tl = fmaxf(tl, fmaxf(s[nt][0], s[nt][1]));
            th = fmaxf(th, fmaxf(s[nt][2], s[nt][3]));
        }
        tl = fmaxf(tl, __shfl_xor_sync(0xffffffffu, tl, 1));
        tl = fmaxf(tl, __shfl_xor_sync(0xffffffffu, tl, 2));
        th = fmaxf(th, __shfl_xor_sync(0xffffffffu, th, 1));
        th = fmaxf(th, __shfl_xor_sync(0xffffffffu, th, 2));
        float mn_l = fmaxf(m_lo, tl), mn_h = fmaxf(m_hi, th);
        float fl = __expf(m_lo - mn_l), fh = __expf(m_hi - mn_h);
        m_lo = mn_l; m_hi = mn_h;

        float sl = 0.f, sh = 0.f;
        #pragma unroll
        for (int nt = 0; nt < 8; nt++) {
            s[nt][0] = __expf(s[nt][0] - m_lo);
            s[nt][1] = __expf(s[nt][1] - m_lo);
            s[nt][2] = __expf(s[nt][2] - m_hi);
            s[nt][3] = __expf(s[nt][3] - m_hi);
            sl += s[nt][0] + s[nt][1];
            sh += s[nt][2] + s[nt][3];
        }
        sl += __shfl_xor_sync(0xffffffffu, sl, 1);
        sl += __shfl_xor_sync(0xffffffffu, sl, 2);
        sh += __shfl_xor_sync(0xffffffffu, sh, 1);
        sh += __shfl_xor_sync(0xffffffffu, sh, 2);
        l_lo = l_lo * fl + sl;
        l_hi = l_hi * fh + sh;
        #pragma unroll
        for (int nt = 0; nt < 8; nt++) {
            o[nt][0] *= fl; o[nt][1] *= fl;
            o[nt][2] *= fh; o[nt][3] *= fh;
        }

        #pragma unroll
        for (int kk = 0; kk < 8; kk++) {
            float t0 = __shfl_sync(0xffffffffu, s[kk][0], src);
            float t1 = __shfl_sync(0xffffffffu, s[kk][1], src);
            float t2 = __shfl_sync(0xffffffffu, s[kk][2], src);
            float t3 = __shfl_sync(0xffffffffu, s[kk][3], src);
            float u0 = __shfl_sync(0xffffffffu, s[kk][0], src2);
            float u1 = __shfl_sync(0xffffffffu, s[kk][1], src2);
            float u2 = __shfl_sync(0xffffffffu, s[kk][2], src2);
            float u3 = __shfl_sync(0xffffffffu, s[kk][3], src2);
            uint32_t pa[4];
            pa[0] = f2tf(odd ? t1 : t0);
            pa[1] = f2tf(odd ? t3 : t2);
            pa[2] = f2tf(odd ? u1 : u0);
            pa[3] = f2tf(odd ? u3 : u2);
            #pragma unroll
            for (int nt = 0; nt < 8; nt++) {
                int krow = kk * 8 + tg;
                int dd = nt * 8 + g;
                uint32_t b0 = Vs[krow * KVPITCH + dd];
                uint32_t b1 = Vs[(krow + 4) * KVPITCH + dd];
                mma_tf32(o[nt], pa, b0, b1);
            }
        }
        __syncthreads();
    }

    float inv_lo = 1.f / l_lo, inv_hi = 1.f / l_hi;
    #pragma unroll
    for (int nt = 0; nt < 8; nt++) {
        int col = h * DH + nt * 8 + 2 * tg;
        size_t r_lo = (size_t)(b * SEQ + q0 + g) * DM + col;
        size_t r_hi = (size_t)(b * SEQ + q0 + g + 8) * DM + col;
        *(float2*)&O[r_lo] = make_float2(o[nt][0] * inv_lo, o[nt][1] * inv_lo);
        *(float2*)&O[r_hi] = make_float2(o[nt][2] * inv_hi, o[nt][3] * inv_hi);
    }
}

// ---------------- launch ----------------
extern "C" void kernel_launch(void* const* d_in, const int* in_sizes, int n_in,
                              void* d_out, int out_size)
{
    const float* query  = (const float*)d_in[0];
    const float* key_in = (const float*)d_in[1];
    const float* value  = (const float*)d_in[2];
    const float* Wq  = (const float*)d_in[3];
    const float* bq  = (const float*)d_in[4];
    const float* Wk  = (const float*)d_in[5];
    const float* bk  = (const float*)d_in[6];
    const float* Wv  = (const float*)d_in[7];
    const float* bv  = (const float*)d_in[8];
    const float* Wo  = (const float*)d_in[9];
    const float* bo  = (const float*)d_in[10];
    const float* Ws1 = (const float*)d_in[11];
    const float* bs1 = (const float*)d_in[12];
    const float* Ws2 = (const float*)d_in[13];
    const float* bs2 = (const float*)d_in[14];
    const float* Wc1 = (const float*)d_in[15];
    const float* bc1 = (const float*)d_in[16];
    const float* Wc2 = (const float*)d_in[17];
    const float* bc2 = (const float*)d_in[18];

    float *pQ, *pK, *pVV, *pVC, *pH, *pVD, *pAO, *pCW, *pWT, *pPART;
    cudaGetSymbolAddress((void**)&pQ,   g_Q);
    cudaGetSymbolAddress((void**)&pK,   g_K);
    cudaGetSymbolAddress((void**)&pVV,  g_VV);
    cudaGetSymbolAddress((void**)&pVC,  g_VC);
    cudaGetSymbolAddress((void**)&pH,   g_H);
    cudaGetSymbolAddress((void**)&pVD,  g_VD);
    cudaGetSymbolAddress((void**)&pAO,  g_AO);
    cudaGetSymbolAddress((void**)&pCW,  g_CW);
    cudaGetSymbolAddress((void**)&pWT,  g_WT);
    cudaGetSymbolAddress((void**)&pPART, g_PART);

    cudaFuncSetAttribute(proj4,    cudaFuncAttributeMaxDynamicSharedMemorySize, SMEM_GEMM);
    cudaFuncSetAttribute(tgemm<0>, cudaFuncAttributeMaxDynamicSharedMemorySize, SMEM_GEMM);
    cudaFuncSetAttribute(tgemm<2>, cudaFuncAttributeMaxDynamicSharedMemorySize, SMEM_GEMM);
    cudaFuncSetAttribute(tgemm<3>, cudaFuncAttributeMaxDynamicSharedMemorySize, SMEM_GEMM);
    cudaFuncSetAttribute(attn_kernel, cudaFuncAttributeMaxDynamicSharedMemorySize, SMEM_ATTN);

    // 0) weights: transpose + tf32 pre-convert (one launch)
    prep_weights<<<1280, dim3(32, 8)>>>(Wq, Wk, Wv, Wo, Ws1, Ws2, pWT);

    // 1) channel gate: full-BW partial mean, then tiny MLP
    mean_part_kernel<<<dim3(8, Bn), 256>>>(value, pPART);
    gate_kernel<<<Bn, 256>>>(pPART, Wc1, bc1, Wc2, bc2, pCW);

    // 2) merged projections Q/K/VV/VC (one launch, 1024 CTAs)
    proj4<<<dim3(DM / 128, MROWS / 128, 4), 256, SMEM_GEMM>>>(
        query, key_in, value, pWT, bq, bk, bv, pCW, pQ, pK, pVV, pVC);

    dim3 g512(DM / 128, MROWS / 128);   // (4, 64)
    dim3 g256(HID / 128, MROWS / 128);  // (2, 64)

    // 3) spatial gate hidden = relu(VV @ Ws1 + bs1)
    tgemm<2><<<g256, 256, SMEM_GEMM>>>(pVV, pWT + WT_S1, bs1, pH, DM, HID, nullptr, nullptr, nullptr);

    // 4) v_dual = VV * sigmoid(H @ Ws2 + bs2) + VC
    tgemm<3><<<g512, 256, SMEM_GEMM>>>(pH, pWT + WT_S2, bs2, pVD, HID, DM, nullptr, pVV, pVC);

    // 5) attention (single wave)
    attn_kernel<<<dim3(SEQ / 128, NH, Bn), 256, SMEM_ATTN>>>(pQ, pK, pVD, pAO);

    // 6) output projection
    tgemm<0><<<g512, 256, SMEM_GEMM>>>(pAO, pWT + WT_O, bo, (float*)d_out, DM, DM, nullptr, nullptr, nullptr);
}

// round 5
// speedup vs baseline: 3.3965x; 1.0615x over previous
#include <cuda_runtime.h>
#include <math.h>
#include <cstdint>

#define Bn   8
#define SEQ  1024
#define DM   512
#define HID  256
#define NH   8
#define DH   64
#define MROWS (Bn*SEQ)

// ---------------- scratch (device globals; no allocation) ----------------
__device__ float g_Q [MROWS*DM];
__device__ float g_K [MROWS*DM];
__device__ float g_VV[MROWS*DM];
__device__ float g_VC[MROWS*DM];
__device__ float g_H [MROWS*HID];
__device__ float g_VD[MROWS*DM];
__device__ float g_AO[MROWS*DM];
__device__ float g_CW[Bn*DM];
__device__ float g_PART[Bn*8*DM];
__device__ float g_WT[4*DM*DM + 2*DM*HID];
__device__ float g_WVB[Bn*DM*DM];       // per-batch channel-scaled Wv (tf32 bits)

#define WT_Q  0
#define WT_K  (DM*DM)
#define WT_V  (2*DM*DM)
#define WT_O  (3*DM*DM)
#define WT_S1 (4*DM*DM)
#define WT_S2 (4*DM*DM + DM*HID)

// ---------------- helpers ----------------
__device__ __forceinline__ uint32_t f2tf(float x) {
    uint32_t u; asm("cvt.rna.tf32.f32 %0, %1;" : "=r"(u) : "f"(x)); return u;
}
__device__ __forceinline__ void mma_tf32(float* c, const uint32_t* a, uint32_t b0, uint32_t b1) {
    asm volatile("mma.sync.aligned.m16n8k8.row.col.f32.tf32.tf32.f32 "
        "{%0,%1,%2,%3}, {%4,%5,%6,%7}, {%8,%9}, {%0,%1,%2,%3};"
        : "+f"(c[0]), "+f"(c[1]), "+f"(c[2]), "+f"(c[3])
        : "r"(a[0]), "r"(a[1]), "r"(a[2]), "r"(a[3]), "r"(b0), "r"(b1));
}
__device__ __forceinline__ uint32_t smem_u32(const void* p) {
    uint32_t a;
    asm("{ .reg .u64 t; cvta.to.shared.u64 t, %1; cvt.u32.u64 %0, t; }" : "=r"(a) : "l"(p));
    return a;
}
__device__ __forceinline__ void cpa16(uint32_t dst, const void* src) {
    asm volatile("cp.async.cg.shared.global [%0], [%1], 16;" :: "r"(dst), "l"(src));
}
#define CP_COMMIT() asm volatile("cp.async.commit_group;" ::: "memory")
#define CP_WAIT3()  asm volatile("cp.async.wait_group 3;" ::: "memory")

// ---------------- prep: all weight transposes + tf32 pre-convert, ONE launch
__global__ void prep_weights(const float* __restrict__ Wq, const float* __restrict__ Wk,
                             const float* __restrict__ Wv, const float* __restrict__ Wo,
                             const float* __restrict__ Ws1, const float* __restrict__ Ws2,
                             float* __restrict__ WT)
{
    int bid = blockIdx.x;           // 1280 blocks total
    const float* in; float* out; int R, C, tb;
    if      (bid < 256)  { in = Wq;  out = WT + WT_Q;  R = DM; C = DM;  tb = bid; }
    else if (bid < 512)  { in = Wk;  out = WT + WT_K;  R = DM; C = DM;  tb = bid - 256; }
    else if (bid < 768)  { in = Wv;  out = WT + WT_V;  R = DM; C = DM;  tb = bid - 512; }
    else if (bid < 1024) { in = Wo;  out = WT + WT_O;  R = DM; C = DM;  tb = bid - 768; }
    else if (bid < 1152) { in = Ws1; out = WT + WT_S1; R = DM; C = HID; tb = bid - 1024; }
    else                 { in = Ws2; out = WT + WT_S2; R = HID; C = DM; tb = bid - 1152; }
    int tilesX = C >> 5;
    int bx = (tb % tilesX) * 32, by = (tb / tilesX) * 32;

    __shared__ float tile[32][33];
    int tx = threadIdx.x, ty = threadIdx.y;      // (32, 8)
    #pragma unroll
    for (int i = 0; i < 32; i += 8)
        tile[ty + i][tx] = in[(size_t)(by + ty + i) * C + bx + tx];
    __syncthreads();
    #pragma unroll
    for (int i = 0; i < 32; i += 8)
        out[(size_t)(bx + ty + i) * R + by + tx] = __uint_as_float(f2tf(tile[tx][ty + i]));
}

// ---------------- mean: partial sums over 128-seq slices
__global__ void mean_part_kernel(const float* __restrict__ value, float* __restrict__ part)
{
    int b = blockIdx.y, s = blockIdx.x;          // (8, 8)
    int t = threadIdx.x;                         // 256
    const float* vb = value + ((size_t)b * SEQ + s * 128) * DM;
    #pragma unroll
    for (int d = t; d < DM; d += 256) {
        float acc = 0.f;
        #pragma unroll 8
        for (int n = 0; n < 128; n++) acc += vb[(size_t)n * DM + d];
        part[(b * 8 + s) * DM + d] = acc;
    }
}

// ---------------- channel gate MLP
__global__ void gate_kernel(const float* __restrict__ part,
                            const float* __restrict__ Wc1, const float* __restrict__ bc1,
                            const float* __restrict__ Wc2, const float* __restrict__ bc2,
                            float* __restrict__ cw)
{
    int b = blockIdx.x;
    int t = threadIdx.x;         // 256
    __shared__ float prof[DM];
    __shared__ float hid[HID];
    for (int d = t; d < DM; d += 256) {
        float s = 0.f;
        #pragma unroll
        for (int k = 0; k < 8; k++) s += part[(b * 8 + k) * DM + d];
        prof[d] = s * (1.0f / SEQ);
    }
    __syncthreads();
    {
        float s = bc1[t];
        #pragma unroll 8
        for (int d = 0; d < DM; d++) s += prof[d] * Wc1[d * HID + t];
        hid[t] = fmaxf(s, 0.f);
    }
    __syncthreads();
    for (int d = t; d < DM; d += 256) {
        float s = bc2[d];
        #pragma unroll 8
        for (int h = 0; h < HID; h++) s += hid[h] * Wc2[h * DM + d];
        cw[b * DM + d] = 1.f / (1.f + __expf(-s));
    }
}

// ---------------- per-batch scaled Wv: WVB[b][n][k] = tf32(WT_V[n][k] * cw[b][k])
__global__ void scale_wv_kernel(const float* __restrict__ WTV, const float* __restrict__ cw,
                                float* __restrict__ WVB)
{
    int b = blockIdx.y;
    int j0 = (blockIdx.x * 256 + threadIdx.x) * 4;
    int k = j0 & (DM - 1);
    float4 w = *(const float4*)&WTV[j0];
    float4 c = *(const float4*)&cw[b * DM + k];
    float4 o;
    o.x = __uint_as_float(f2tf(w.x * c.x));
    o.y = __uint_as_float(f2tf(w.y * c.y));
    o.z = __uint_as_float(f2tf(w.z * c.z));
    o.w = __uint_as_float(f2tf(w.w * c.w));
    *(float4*)&WVB[(size_t)b * DM * DM + j0] = o;
}

// ---------------- tf32 mma GEMM body, cp.async 5-stage pipeline
// C[M,N] = epi(A[M,K] @ B[N,K]^T + bias); A raw fp32 (cvt at frag load), B pre-tf32
// MODE 0: plain   MODE 2: relu   MODE 3: C = E1 * sigmoid(acc+bias) + E2
#define PITCH 20
#define TWRD  (128*PITCH)              // 2560 words per tile
#define STGW  (2*TWRD)                 // 5120 words per stage (A+B)
#define NSTG  5
#define SMEM_GEMM (NSTG*STGW*4)        // 102400 B

template<int MODE>
__device__ __forceinline__
void gemm_body(const float* __restrict__ A, const float* __restrict__ B,
               const float* __restrict__ bias, float* __restrict__ C,
               int Kd, int Nd,
               const float* __restrict__ E1, const float* __restrict__ E2,
               int m0, int n0)
{
    extern __shared__ __align__(16) uint32_t usm[];
    const uint32_t sb = smem_u32(usm);
    const int t    = threadIdx.x;
    const int lane = t & 31;
    const int wid  = t >> 5;
    const int g    = lane >> 2;
    const int tg   = lane & 3;
    const int wm   = wid & 3;
    const int wn   = wid >> 2;
    const int NK   = Kd / 16;

    float acc[2][8][4];
    #pragma unroll
    for (int mt = 0; mt < 2; mt++)
        #pragma unroll
        for (int nt = 0; nt < 8; nt++)
            #pragma unroll
            for (int j = 0; j < 4; j++) acc[mt][nt][j] = 0.f;

    const int prow = t >> 2, pq = (t & 3) * 4;   // producer: 2 rows per thread per tile
    auto issue = [&](int kc) {
        if (kc < NK) {
            const int k0 = kc * 16;
            const uint32_t ab = sb + (kc % NSTG) * (STGW * 4);
            #pragma unroll
            for (int i = 0; i < 2; i++) {
                int row = prow + i * 64;
                uint32_t soff = (row * PITCH + pq) * 4;
                cpa16(ab + soff,             &A[(size_t)(m0 + row) * Kd + k0 + pq]);
                cpa16(ab + TWRD * 4 + soff,  &B[(size_t)(n0 + row) * Kd + k0 + pq]);
            }
        }
        CP_COMMIT();
    };

    issue(0); issue(1); issue(2); issue(3);

    for (int kc = 0; kc < NK; kc++) {
        CP_WAIT3();
        __syncthreads();
        issue(kc + 4);

        const float*    Af = (const float*)(usm + (kc % NSTG) * STGW);
        const uint32_t* Bw = usm + (kc % NSTG) * STGW + TWRD;
        #pragma unroll
        for (int ks = 0; ks < 2; ks++) {
            const int c0 = ks * 8 + tg;
            uint32_t af[2][4];
            #pragma unroll
            for (int mt = 0; mt < 2; mt++) {
                int r0 = wm * 32 + mt * 16 + g;
                af[mt][0] = f2tf(Af[r0 * PITCH + c0]);
                af[mt][1] = f2tf(Af[(r0 + 8) * PITCH + c0]);
                af[mt][2] = f2tf(Af[r0 * PITCH + c0 + 4]);
                af[mt][3] = f2tf(Af[(r0 + 8) * PITCH + c0 + 4]);
            }
            #pragma unroll
            for (int nt = 0; nt < 8; nt++) {
                int nn = wn * 64 + nt * 8 + g;
                uint32_t b0 = Bw[nn * PITCH + c0];
                uint32_t b1 = Bw[nn * PITCH + c0 + 4];
                mma_tf32(acc[0][nt], af[0], b0, b1);
                mma_tf32(acc[1][nt], af[1], b0, b1);
            }
        }
    }

    #pragma unroll
    for (int mt = 0; mt < 2; mt++) {
        int r_lo = m0 + wm * 32 + mt * 16 + g;
        int r_hi = r_lo + 8;
        #pragma unroll
        for (int nt = 0; nt < 8; nt++) {
            int col = n0 + wn * 64 + nt * 8 + 2 * tg;
            float bx = bias[col], by = bias[col + 1];
            float v0 = acc[mt][nt][0] + bx;
            float v1 = acc[mt][nt][1] + by;
            float v2 = acc[mt][nt][2] + bx;
            float v3 = acc[mt][nt][3] + by;
            if (MODE == 2) {
                v0 = fmaxf(v0, 0.f); v1 = fmaxf(v1, 0.f);
                v2 = fmaxf(v2, 0.f); v3 = fmaxf(v3, 0.f);
            }
            if (MODE == 3) {
                size_t i_lo = (size_t)r_lo * Nd + col;
                size_t i_hi = (size_t)r_hi * Nd + col;
                float2 e1l = *(const float2*)&E1[i_lo];
                float2 e2l = *(const float2*)&E2[i_lo];
                float2 e1h = *(const float2*)&E1[i_hi];
                float2 e2h = *(const float2*)&E2[i_hi];
                v0 = e1l.x / (1.f + __expf(-v0)) + e2l.x;
                v1 = e1l.y / (1.f + __expf(-v1)) + e2l.y;
                v2 = e1h.x / (1.f + __expf(-v2)) + e2h.x;
                v3 = e1h.y / (1.f + __expf(-v3)) + e2h.y;
            }
            *(float2*)&C[(size_t)r_lo * Nd + col] = make_float2(v0, v1);
            *(float2*)&C[(size_t)r_hi * Nd + col] = make_float2(v2, v3);
        }
    }
}

template<int MODE>
__global__ __launch_bounds__(256, 2)
void tgemm(const float* __restrict__ A, const float* __restrict__ B,
           const float* __restrict__ bias, float* __restrict__ C,
           int Kd, int Nd,
           const float* __restrict__ E1, const float* __restrict__ E2)
{
    gemm_body<MODE>(A, B, bias, C, Kd, Nd, E1, E2, blockIdx.y * 128, blockIdx.x * 128);
}

// merged Q/K/VV/VC projections
__global__ __launch_bounds__(256, 2)
void proj4(const float* __restrict__ query, const float* __restrict__ key_in,
           const float* __restrict__ value, const float* __restrict__ WTb,
           const float* __restrict__ WVB,
           const float* __restrict__ bq, const float* __restrict__ bk,
           const float* __restrict__ bv,
           float* __restrict__ oQ, float* __restrict__ oK,
           float* __restrict__ oVV, float* __restrict__ oVC)
{
    const int z = blockIdx.z;
    const int m0 = blockIdx.y * 128, n0 = blockIdx.x * 128;
    const int bb = blockIdx.y >> 3;
    if (z == 0)
        gemm_body<0>(query,  WTb + WT_Q, bq, oQ,  DM, DM, nullptr, nullptr, m0, n0);
    else if (z == 1)
        gemm_body<0>(key_in, WTb + WT_K, bk, oK,  DM, DM, nullptr, nullptr, m0, n0);
    else if (z == 2)
        gemm_body<0>(value,  WTb + WT_V, bv, oVV, DM, DM, nullptr, nullptr, m0, n0);
    else
        gemm_body<0>(value,  WVB + (size_t)bb * DM * DM, bv, oVC, DM, DM, nullptr, nullptr, m0, n0);
}

// ---------------- flash attention (tf32 mma, 32-token KV chunks, 2 CTA/SM)
#define KVPITCH 72
#define KVTOK   32
#define SMEM_ATTN (2*KVTOK*KVPITCH*4)   // 18432 B

__global__ __launch_bounds__(256, 2)
void attn_kernel(const float* __restrict__ Q, const float* __restrict__ Kp,
                 const float* __restrict__ V, float* __restrict__ O)
{
    extern __shared__ uint32_t usm[];
    uint32_t* Ks = usm;
    uint32_t* Vs = usm + KVTOK * KVPITCH;

    const int qt = blockIdx.x;
    const int h  = blockIdx.y;
    const int b  = blockIdx.z;
    const int t  = threadIdx.x;
    const int lane = t & 31;
    const int wid  = t >> 5;
    const int g  = lane >> 2;
    const int tg = lane & 3;
    const int q0 = qt * 128 + wid * 16;

    uint32_t aq[8][4];
    {
        const float* Qb = Q + ((size_t)(b * SEQ + q0)) * DM + h * DH;
        #pragma unroll
        for (int ks = 0; ks < 8; ks++) {
            int c0 = ks * 8 + tg;
            aq[ks][0] = f2tf(0.125f * Qb[(size_t)g * DM + c0]);
            aq[ks][1] = f2tf(0.125f * Qb[(size_t)(g + 8) * DM + c0]);
            aq[ks][2] = f2tf(0.125f * Qb[(size_t)g * DM + c0 + 4]);
            aq[ks][3] = f2tf(0.125f * Qb[(size_t)(g + 8) * DM + c0 + 4]);
        }
    }

    float o[8][4];
    #pragma unroll
    for (int nt = 0; nt < 8; nt++)
        #pragma unroll
        for (int j = 0; j < 4; j++) o[nt][j] = 0.f;
    float m_lo = -1e30f, m_hi = -1e30f, l_lo = 0.f, l_hi = 0.f;

    const int src  = (lane & ~3) | (tg >> 1);
    const int src2 = src + 2;
    const bool odd = (lane & 1);

    for (int kt = 0; kt < SEQ / KVTOK; kt++) {
        #pragma unroll
        for (int i = 0; i < 2; i++) {
            int idx = t + i * 256;
            int tok = idx >> 4, qd = idx & 15;
            size_t gaddr = ((size_t)(b * SEQ + kt * KVTOK + tok)) * DM + h * DH + qd * 4;
            float4 kv = *(const float4*)&Kp[gaddr];
            float4 vv = *(const float4*)&V[gaddr];
            uint4 uk; uk.x = f2tf(kv.x); uk.y = f2tf(kv.y); uk.z = f2tf(kv.z); uk.w = f2tf(kv.w);
            uint4 uv; uv.x = f2tf(vv.x); uv.y = f2tf(vv.y); uv.z = f2tf(vv.z); uv.w = f2tf(vv.w);
            int sw = ((tok >> 2) & 1) << 2;
            *(uint4*)&Ks[tok * KVPITCH + ((qd * 4) ^ sw)] = uk;
            *(uint4*)&Vs[tok * KVPITCH + qd * 4] = uv;
        }
        __syncthreads();

        float s[4][4];
        #pragma unroll
        for (int nt = 0; nt < 4; nt++)
            #pragma unroll
            for (int j = 0; j < 4; j++) s[nt][j] = 0.f;
        #pragma unroll
        for (int ks = 0; ks < 8; ks++) {
            #pragma unroll
            for (int nt = 0; nt < 4; nt++) {
                int key = nt * 8 + g;
                int d0 = ks * 8 + tg;
                int sw = ((key >> 2) & 1) << 2;
                uint32_t b0 = Ks[key * KVPITCH + (d0 ^ sw)];
                uint32_t b1 = Ks[key * KVPITCH + ((d0 + 4) ^ sw)];
                mma_tf32(s[nt], aq[ks], b0, b1);
            }
        }

        float tl = -1e30f, th = -1e30f;
        #pragma unroll
        for (int nt = 0; nt < 4; nt++) {
            tl = fmaxf(tl, fmaxf(s[nt][0], s[nt][1]));
            th = fmaxf(th, fmaxf(s[nt][2], s[nt][3]));
        }
        tl = fmaxf(tl, __shfl_xor_sync(0xffffffffu, tl, 1));
        tl = fmaxf(tl, __shfl_xor_sync(0xffffffffu, tl, 2));
        th = fmaxf(th, __shfl_xor_sync(0xffffffffu, th, 1));
        th = fmaxf(th, __shfl_xor_sync(0xffffffffu, th, 2));
        float mn_l = fmaxf(m_lo, tl), mn_h = fmaxf(m_hi, th);
        float fl = __expf(m_lo - mn_l), fh = __expf(m_hi - mn_h);
        m_lo = mn_l; m_hi = mn_h;

        float sl = 0.f, sh = 0.f;
        #pragma unroll
        for (int nt = 0; nt < 4; nt++) {
            s[nt][0] = __expf(s[nt][0] - m_lo);
            s[nt][1] = __expf(s[nt][1] - m_lo);
            s[nt][2] = __expf(s[nt][2] - m_hi);
            s[nt][3] = __expf(s[nt][3] - m_hi);
            sl += s[nt][0] + s[nt][1];
            sh += s[nt][2] + s[nt][3];
        }
        sl += __shfl_xor_sync(0xffffffffu, sl, 1);
        sl += __shfl_xor_sync(0xffffffffu, sl, 2);
        sh += __shfl_xor_sync(0xffffffffu, sh, 1);
        sh += __shfl_xor_sync(0xffffffffu, sh, 2);
        l_lo = l_lo * fl + sl;
        l_hi = l_hi * fh + sh;
        #pragma unroll
        for (int nt = 0; nt < 8; nt++) {
            o[nt][0] *= fl; o[nt][1] *= fl;
            o[nt][2] *= fh; o[nt][3] *= fh;
        }

        #pragma unroll
        for (int kk = 0; kk < 4; kk++) {
            float t0 = __shfl_sync(0xffffffffu, s[kk][0], src);
            float t1 = __shfl_sync(0xffffffffu, s[kk][1], src);
            float t2 = __shfl_sync(0xffffffffu, s[kk][2], src);
            float t3 = __shfl_sync(0xffffffffu, s[kk][3], src);
            float u0 = __shfl_sync(0xffffffffu, s[kk][0], src2);
            float u1 = __shfl_sync(0xffffffffu, s[kk][1], src2);
            float u2 = __shfl_sync(0xffffffffu, s[kk][2], src2);
            float u3 = __shfl_sync(0xffffffffu, s[kk][3], src2);
            uint32_t pa[4];
            pa[0] = f2tf(odd ? t1 : t0);
            pa[1] = f2tf(odd ? t3 : t2);
            pa[2] = f2tf(odd ? u1 : u0);
            pa[3] = f2tf(odd ? u3 : u2);
            #pragma unroll
            for (int nt = 0; nt < 8; nt++) {
                int krow = kk * 8 + tg;
                int dd = nt * 8 + g;
                uint32_t b0 = Vs[krow * KVPITCH + dd];
                uint32_t b1 = Vs[(krow + 4) * KVPITCH + dd];
                mma_tf32(o[nt], pa, b0, b1);
            }
        }
        __syncthreads();
    }

    float inv_lo = 1.f / l_lo, inv_hi = 1.f / l_hi;
    #pragma unroll
    for (int nt = 0; nt < 8; nt++) {
        int col = h * DH + nt * 8 + 2 * tg;
        size_t r_lo = (size_t)(b * SEQ + q0 + g) * DM + col;
        size_t r_hi = (size_t)(b * SEQ + q0 + g + 8) * DM + col;
        *(float2*)&O[r_lo] = make_float2(o[nt][0] * inv_lo, o[nt][1] * inv_lo);
        *(float2*)&O[r_hi] = make_float2(o[nt][2] * inv_hi, o[nt][3] * inv_hi);
    }
}

// ---------------- launch ----------------
extern "C" void kernel_launch(void* const* d_in, const int* in_sizes, int n_in,
                              void* d_out, int out_size)
{
    const float* query  = (const float*)d_in[0];
    const float* key_in = (const float*)d_in[1];
    const float* value  = (const float*)d_in[2];
    const float* Wq  = (const float*)d_in[3];
    const float* bq  = (const float*)d_in[4];
    const float* Wk  = (const float*)d_in[5];
    const float* bk  = (const float*)d_in[6];
    const float* Wv  = (const float*)d_in[7];
    const float* bv  = (const float*)d_in[8];
    const float* Wo  = (const float*)d_in[9];
    const float* bo  = (const float*)d_in[10];
    const float* Ws1 = (const float*)d_in[11];
    const float* bs1 = (const float*)d_in[12];
    const float* Ws2 = (const float*)d_in[13];
    const float* bs2 = (const float*)d_in[14];
    const float* Wc1 = (const float*)d_in[15];
    const float* bc1 = (const float*)d_in[16];
    const float* Wc2 = (const float*)d_in[17];
    const float* bc2 = (const float*)d_in[18];

    float *pQ, *pK, *pVV, *pVC, *pH, *pVD, *pAO, *pCW, *pWT, *pPART, *pWVB;
    cudaGetSymbolAddress((void**)&pQ,    g_Q);
    cudaGetSymbolAddress((void**)&pK,    g_K);
    cudaGetSymbolAddress((void**)&pVV,   g_VV);
    cudaGetSymbolAddress((void**)&pVC,   g_VC);
    cudaGetSymbolAddress((void**)&pH,    g_H);
    cudaGetSymbolAddress((void**)&pVD,   g_VD);
    cudaGetSymbolAddress((void**)&pAO,   g_AO);
    cudaGetSymbolAddress((void**)&pCW,   g_CW);
    cudaGetSymbolAddress((void**)&pWT,   g_WT);
    cudaGetSymbolAddress((void**)&pPART, g_PART);
    cudaGetSymbolAddress((void**)&pWVB,  g_WVB);

    cudaFuncSetAttribute(proj4,    cudaFuncAttributeMaxDynamicSharedMemorySize, SMEM_GEMM);
    cudaFuncSetAttribute(tgemm<0>, cudaFuncAttributeMaxDynamicSharedMemorySize, SMEM_GEMM);
    cudaFuncSetAttribute(tgemm<2>, cudaFuncAttributeMaxDynamicSharedMemorySize, SMEM_GEMM);
    cudaFuncSetAttribute(tgemm<3>, cudaFuncAttributeMaxDynamicSharedMemorySize, SMEM_GEMM);

    // 0) weights: transpose + tf32 pre-convert
    prep_weights<<<1280, dim3(32, 8)>>>(Wq, Wk, Wv, Wo, Ws1, Ws2, pWT);

    // 1) channel gate: full-BW partial mean, tiny MLP, per-batch scaled Wv
    mean_part_kernel<<<dim3(8, Bn), 256>>>(value, pPART);
    gate_kernel<<<Bn, 256>>>(pPART, Wc1, bc1, Wc2, bc2, pCW);
    scale_wv_kernel<<<dim3(DM * DM / 1024, Bn), 256>>>(pWT + WT_V, pCW, pWVB);

    // 2) merged projections Q/K/VV/VC
    proj4<<<dim3(DM / 128, MROWS / 128, 4), 256, SMEM_GEMM>>>(
        query, key_in, value, pWT, pWVB, bq, bk, bv, pQ, pK, pVV, pVC);

    dim3 g512(DM / 128, MROWS / 128);   // (4, 64)
    dim3 g256(HID / 128, MROWS / 128);  // (2, 64)

    // 3) spatial gate hidden = relu(VV @ Ws1 + bs1)
    tgemm<2><<<g256, 256, SMEM_GEMM>>>(pVV, pWT + WT_S1, bs1, pH, DM, HID, nullptr, nullptr);

    // 4) v_dual = VV * sigmoid(H @ Ws2 + bs2) + VC
    tgemm<3><<<g512, 256, SMEM_GEMM>>>(pH, pWT + WT_S2, bs2, pVD, HID, DM, pVV, pVC);

    // 5) attention
    attn_kernel<<<dim3(SEQ / 128, NH, Bn), 256, SMEM_ATTN>>>(pQ, pK, pVD, pAO);

    // 6) output projection
    tgemm<0><<<g512, 256, SMEM_GEMM>>>(pAO, pWT + WT_O, bo, (float*)d_out, DM, DM, nullptr, nullptr);
}

// round 6
// speedup vs baseline: 3.6398x; 1.0716x over previous
#include <cuda_runtime.h>
#include <math.h>
#include <cstdint>

#define Bn   8
#define SEQ  1024
#define DM   512
#define HID  256
#define NH   8
#define DH   64
#define MROWS (Bn*SEQ)

// ---------------- scratch (device globals; no allocation) ----------------
__device__ float g_Q [MROWS*DM];
__device__ float g_K [MROWS*DM];
__device__ float g_VV[MROWS*DM];
__device__ float g_VC[MROWS*DM];
__device__ float g_H [MROWS*HID];
__device__ float g_VD[MROWS*DM];
__device__ float g_AO[MROWS*DM];
__device__ float g_CW[Bn*DM];
__device__ float g_PART[Bn*8*DM];
__device__ float g_WT[4*DM*DM + 2*DM*HID];
__device__ float g_WVB[Bn*DM*DM];       // per-batch channel-scaled Wv (tf32 bits)

#define WT_Q  0
#define WT_K  (DM*DM)
#define WT_V  (2*DM*DM)
#define WT_O  (3*DM*DM)
#define WT_S1 (4*DM*DM)
#define WT_S2 (4*DM*DM + DM*HID)

// ---------------- helpers ----------------
__device__ __forceinline__ uint32_t f2tf(float x) {
    uint32_t u; asm("cvt.rna.tf32.f32 %0, %1;" : "=r"(u) : "f"(x)); return u;
}
__device__ __forceinline__ void mma_tf32(float* c, const uint32_t* a, uint32_t b0, uint32_t b1) {
    asm volatile("mma.sync.aligned.m16n8k8.row.col.f32.tf32.tf32.f32 "
        "{%0,%1,%2,%3}, {%4,%5,%6,%7}, {%8,%9}, {%0,%1,%2,%3};"
        : "+f"(c[0]), "+f"(c[1]), "+f"(c[2]), "+f"(c[3])
        : "r"(a[0]), "r"(a[1]), "r"(a[2]), "r"(a[3]), "r"(b0), "r"(b1));
}
__device__ __forceinline__ uint32_t smem_u32(const void* p) {
    uint32_t a;
    asm("{ .reg .u64 t; cvta.to.shared.u64 t, %1; cvt.u32.u64 %0, t; }" : "=r"(a) : "l"(p));
    return a;
}
__device__ __forceinline__ void cpa16(uint32_t dst, const void* src) {
    asm volatile("cp.async.cg.shared.global [%0], [%1], 16;" :: "r"(dst), "l"(src));
}
#define CP_COMMIT() asm volatile("cp.async.commit_group;" ::: "memory")
#define CP_WAIT1()  asm volatile("cp.async.wait_group 1;" ::: "memory")

// ---------------- prep: weight transposes + tf32 pre-convert ----------------
__global__ void prep_weights(const float* __restrict__ Wq, const float* __restrict__ Wk,
                             const float* __restrict__ Wv, const float* __restrict__ Wo,
                             const float* __restrict__ Ws1, const float* __restrict__ Ws2,
                             float* __restrict__ WT)
{
    int bid = blockIdx.x;           // 1280 blocks total
    const float* in; float* out; int R, C, tb;
    if      (bid < 256)  { in = Wq;  out = WT + WT_Q;  R = DM; C = DM;  tb = bid; }
    else if (bid < 512)  { in = Wk;  out = WT + WT_K;  R = DM; C = DM;  tb = bid - 256; }
    else if (bid < 768)  { in = Wv;  out = WT + WT_V;  R = DM; C = DM;  tb = bid - 512; }
    else if (bid < 1024) { in = Wo;  out = WT + WT_O;  R = DM; C = DM;  tb = bid - 768; }
    else if (bid < 1152) { in = Ws1; out = WT + WT_S1; R = DM; C = HID; tb = bid - 1024; }
    else                 { in = Ws2; out = WT + WT_S2; R = HID; C = DM; tb = bid - 1152; }
    int tilesX = C >> 5;
    int bx = (tb % tilesX) * 32, by = (tb / tilesX) * 32;

    __shared__ float tile[32][33];
    int tx = threadIdx.x, ty = threadIdx.y;      // (32, 8)
    #pragma unroll
    for (int i = 0; i < 32; i += 8)
        tile[ty + i][tx] = in[(size_t)(by + ty + i) * C + bx + tx];
    __syncthreads();
    #pragma unroll
    for (int i = 0; i < 32; i += 8)
        out[(size_t)(bx + ty + i) * R + by + tx] = __uint_as_float(f2tf(tile[tx][ty + i]));
}

// ---------------- mean: partial sums over 128-seq slices ----------------
__global__ void mean_part_kernel(const float* __restrict__ value, float* __restrict__ part)
{
    int b = blockIdx.y, s = blockIdx.x;          // (8, 8)
    int t = threadIdx.x;                         // 256
    const float* vb = value + ((size_t)b * SEQ + s * 128) * DM;
    #pragma unroll
    for (int d = t; d < DM; d += 256) {
        float acc = 0.f;
        #pragma unroll 8
        for (int n = 0; n < 128; n++) acc += vb[(size_t)n * DM + d];
        part[(b * 8 + s) * DM + d] = acc;
    }
}

// ---------------- channel gate MLP ----------------
__global__ void gate_kernel(const float* __restrict__ part,
                            const float* __restrict__ Wc1, const float* __restrict__ bc1,
                            const float* __restrict__ Wc2, const float* __restrict__ bc2,
                            float* __restrict__ cw)
{
    int b = blockIdx.x;
    int t = threadIdx.x;         // 256
    __shared__ float prof[DM];
    __shared__ float hid[HID];
    for (int d = t; d < DM; d += 256) {
        float s = 0.f;
        #pragma unroll
        for (int k = 0; k < 8; k++) s += part[(b * 8 + k) * DM + d];
        prof[d] = s * (1.0f / SEQ);
    }
    __syncthreads();
    {
        float s = bc1[t];
        #pragma unroll 8
        for (int d = 0; d < DM; d++) s += prof[d] * Wc1[d * HID + t];
        hid[t] = fmaxf(s, 0.f);
    }
    __syncthreads();
    for (int d = t; d < DM; d += 256) {
        float s = bc2[d];
        #pragma unroll 8
        for (int h = 0; h < HID; h++) s += hid[h] * Wc2[h * DM + d];
        cw[b * DM + d] = 1.f / (1.f + __expf(-s));
    }
}

// ---------------- per-batch scaled Wv ----------------
__global__ void scale_wv_kernel(const float* __restrict__ WTV, const float* __restrict__ cw,
                                float* __restrict__ WVB)
{
    int b = blockIdx.y;
    int j0 = (blockIdx.x * 256 + threadIdx.x) * 4;
    int k = j0 & (DM - 1);
    float4 w = *(const float4*)&WTV[j0];
    float4 c = *(const float4*)&cw[b * DM + k];
    float4 o;
    o.x = __uint_as_float(f2tf(w.x * c.x));
    o.y = __uint_as_float(f2tf(w.y * c.y));
    o.z = __uint_as_float(f2tf(w.z * c.z));
    o.w = __uint_as_float(f2tf(w.w * c.w));
    *(float4*)&WVB[(size_t)b * DM * DM + j0] = o;
}

// ---------------- tf32 mma GEMM, K-chunk 32, 3-stage cp.async ring
// C[M,N] = epi(A[M,K] @ B[N,K]^T + bias); A raw fp32 (cvt at frag), B pre-tf32
// MODE 0: plain   MODE 2: relu   MODE 3: C = E1 * sigmoid(acc+bias) + E2
// RND: round outputs to tf32 (RNA) so consumers can skip cvt
#define PITCH 36
#define TWRD  (128*PITCH)              // 4608 words per tile
#define STGW  (2*TWRD)                 // 9216 words per stage (A+B)
#define NSTG  3
#define SMEM_GEMM (NSTG*STGW*4)        // 110592 B

template<int MODE, bool RND>
__device__ __forceinline__
void gemm_body(const float* __restrict__ A, const float* __restrict__ B,
               const float* __restrict__ bias, float* __restrict__ C,
               int Kd, int Nd,
               const float* __restrict__ E1, const float* __restrict__ E2,
               int m0, int n0)
{
    extern __shared__ __align__(16) uint32_t usm[];
    const uint32_t sb = smem_u32(usm);
    const int t    = threadIdx.x;
    const int lane = t & 31;
    const int wid  = t >> 5;
    const int g    = lane >> 2;
    const int tg   = lane & 3;
    const int wm   = wid & 3;
    const int wn   = wid >> 2;
    const int NK   = Kd / 32;

    float acc[2][8][4];
    #pragma unroll
    for (int mt = 0; mt < 2; mt++)
        #pragma unroll
        for (int nt = 0; nt < 8; nt++)
            #pragma unroll
            for (int j = 0; j < 4; j++) acc[mt][nt][j] = 0.f;

    auto issue = [&](int kc) {
        if (kc < NK) {
            const int k0 = kc * 32;
            const uint32_t ab = sb + (kc % NSTG) * (STGW * 4);
            #pragma unroll
            for (int i = 0; i < 4; i++) {
                int idx = t + i * 256;
                int row = idx >> 3, q = idx & 7;
                uint32_t soff = (row * PITCH + q * 4) * 4;
                cpa16(ab + soff,            &A[(size_t)(m0 + row) * Kd + k0 + q * 4]);
                cpa16(ab + TWRD * 4 + soff, &B[(size_t)(n0 + row) * Kd + k0 + q * 4]);
            }
        }
        CP_COMMIT();
    };

    issue(0); issue(1);

    for (int kc = 0; kc < NK; kc++) {
        CP_WAIT1();
        __syncthreads();
        issue(kc + 2);

        const float*    Af = (const float*)(usm + (kc % NSTG) * STGW);
        const uint32_t* Bw = usm + (kc % NSTG) * STGW + TWRD;
        #pragma unroll
        for (int ks = 0; ks < 4; ks++) {
            const int c0 = ks * 8 + tg;
            uint32_t af[2][4];
            #pragma unroll
            for (int mt = 0; mt < 2; mt++) {
                int r0 = wm * 32 + mt * 16 + g;
                af[mt][0] = f2tf(Af[r0 * PITCH + c0]);
                af[mt][1] = f2tf(Af[(r0 + 8) * PITCH + c0]);
                af[mt][2] = f2tf(Af[r0 * PITCH + c0 + 4]);
                af[mt][3] = f2tf(Af[(r0 + 8) * PITCH + c0 + 4]);
            }
            #pragma unroll
            for (int nt = 0; nt < 8; nt++) {
                int nn = wn * 64 + nt * 8 + g;
                uint32_t b0 = Bw[nn * PITCH + c0];
                uint32_t b1 = Bw[nn * PITCH + c0 + 4];
                mma_tf32(acc[0][nt], af[0], b0, b1);
                mma_tf32(acc[1][nt], af[1], b0, b1);
            }
        }
    }

    #pragma unroll
    for (int mt = 0; mt < 2; mt++) {
        int r_lo = m0 + wm * 32 + mt * 16 + g;
        int r_hi = r_lo + 8;
        #pragma unroll
        for (int nt = 0; nt < 8; nt++) {
            int col = n0 + wn * 64 + nt * 8 + 2 * tg;
            float bx = bias[col], by = bias[col + 1];
            float v0 = acc[mt][nt][0] + bx;
            float v1 = acc[mt][nt][1] + by;
            float v2 = acc[mt][nt][2] + bx;
            float v3 = acc[mt][nt][3] + by;
            if (MODE == 2) {
                v0 = fmaxf(v0, 0.f); v1 = fmaxf(v1, 0.f);
                v2 = fmaxf(v2, 0.f); v3 = fmaxf(v3, 0.f);
            }
            if (MODE == 3) {
                size_t i_lo = (size_t)r_lo * Nd + col;
                size_t i_hi = (size_t)r_hi * Nd + col;
                float2 e1l = *(const float2*)&E1[i_lo];
                float2 e2l = *(const float2*)&E2[i_lo];
                float2 e1h = *(const float2*)&E1[i_hi];
                float2 e2h = *(const float2*)&E2[i_hi];
                v0 = e1l.x / (1.f + __expf(-v0)) + e2l.x;
                v1 = e1l.y / (1.f + __expf(-v1)) + e2l.y;
                v2 = e1h.x / (1.f + __expf(-v2)) + e2h.x;
                v3 = e1h.y / (1.f + __expf(-v3)) + e2h.y;
            }
            if (RND) {
                v0 = __uint_as_float(f2tf(v0));
                v1 = __uint_as_float(f2tf(v1));
                v2 = __uint_as_float(f2tf(v2));
                v3 = __uint_as_float(f2tf(v3));
            }
            *(float2*)&C[(size_t)r_lo * Nd + col] = make_float2(v0, v1);
            *(float2*)&C[(size_t)r_hi * Nd + col] = make_float2(v2, v3);
        }
    }
}

template<int MODE, bool RND>
__global__ __launch_bounds__(256, 2)
void tgemm(const float* __restrict__ A, const float* __restrict__ B,
           const float* __restrict__ bias, float* __restrict__ C,
           int Kd, int Nd,
           const float* __restrict__ E1, const float* __restrict__ E2)
{
    gemm_body<MODE, RND>(A, B, bias, C, Kd, Nd, E1, E2, blockIdx.y * 128, blockIdx.x * 128);
}

// merged Q/K/VV/VC projections (Q,K rounded to tf32 for attention)
__global__ __launch_bounds__(256, 2)
void proj4(const float* __restrict__ query, const float* __restrict__ key_in,
           const float* __restrict__ value, const float* __restrict__ WTb,
           const float* __restrict__ WVB,
           const float* __restrict__ bq, const float* __restrict__ bk,
           const float* __restrict__ bv,
           float* __restrict__ oQ, float* __restrict__ oK,
           float* __restrict__ oVV, float* __restrict__ oVC)
{
    const int z = blockIdx.z;
    const int m0 = blockIdx.y * 128, n0 = blockIdx.x * 128;
    const int bb = blockIdx.y >> 3;
    if (z == 0)
        gemm_body<0, true >(query,  WTb + WT_Q, bq, oQ,  DM, DM, nullptr, nullptr, m0, n0);
    else if (z == 1)
        gemm_body<0, true >(key_in, WTb + WT_K, bk, oK,  DM, DM, nullptr, nullptr, m0, n0);
    else if (z == 2)
        gemm_body<0, false>(value,  WTb + WT_V, bv, oVV, DM, DM, nullptr, nullptr, m0, n0);
    else
        gemm_body<0, false>(value,  WVB + (size_t)bb * DM * DM, bv, oVC, DM, DM, nullptr, nullptr, m0, n0);
}

// ---------------- flash attention: tf32 mma, 3-stage cp.async KV ring
// K, V(=VD), Q are pre-rounded tf32 bits -> no cvt in the hot loop
#define KVPITCH 72
#define KVTOK   32
#define KVSTGW  (2*KVTOK*KVPITCH)       // words per stage (K+V)
#define SMEM_ATTN (NSTG*KVSTGW*4)       // 55296 B

__global__ __launch_bounds__(256, 2)
void attn_kernel(const float* __restrict__ Q, const float* __restrict__ Kp,
                 const float* __restrict__ V, float* __restrict__ O)
{
    extern __shared__ __align__(16) uint32_t usm[];
    const uint32_t sb = smem_u32(usm);

    const int qt = blockIdx.x;
    const int h  = blockIdx.y;
    const int b  = blockIdx.z;
    const int t  = threadIdx.x;
    const int lane = t & 31;
    const int wid  = t >> 5;
    const int g  = lane >> 2;
    const int tg = lane & 3;
    const int q0 = qt * 128 + wid * 16;

    uint32_t aq[8][4];
    {
        const float* Qb = Q + ((size_t)(b * SEQ + q0)) * DM + h * DH;
        #pragma unroll
        for (int ks = 0; ks < 8; ks++) {
            int c0 = ks * 8 + tg;
            aq[ks][0] = f2tf(0.125f * Qb[(size_t)g * DM + c0]);
            aq[ks][1] = f2tf(0.125f * Qb[(size_t)(g + 8) * DM + c0]);
            aq[ks][2] = f2tf(0.125f * Qb[(size_t)g * DM + c0 + 4]);
            aq[ks][3] = f2tf(0.125f * Qb[(size_t)(g + 8) * DM + c0 + 4]);
        }
    }

    float o[8][4];
    #pragma unroll
    for (int nt = 0; nt < 8; nt++)
        #pragma unroll
        for (int j = 0; j < 4; j++) o[nt][j] = 0.f;
    float m_lo = -1e30f, m_hi = -1e30f, l_lo = 0.f, l_hi = 0.f;

    const int src  = (lane & ~3) | (tg >> 1);
    const int src2 = src + 2;
    const bool odd = (lane & 1);

    auto issue = [&](int kt) {
        if (kt < SEQ / KVTOK) {
            const uint32_t ab = sb + (kt % NSTG) * (KVSTGW * 4);
            #pragma unroll
            for (int i = 0; i < 2; i++) {
                int idx = t + i * 256;
                int tok = idx >> 4, qd = idx & 15;
                size_t gaddr = ((size_t)(b * SEQ + kt * KVTOK + tok)) * DM + h * DH + qd * 4;
                int sw = ((tok >> 2) & 1) << 2;
                cpa16(ab + (tok * KVPITCH + ((qd * 4) ^ sw)) * 4, &Kp[gaddr]);
                cpa16(ab + (KVTOK * KVPITCH + tok * KVPITCH + qd * 4) * 4, &V[gaddr]);
            }
        }
        CP_COMMIT();
    };

    issue(0); issue(1);

    for (int kt = 0; kt < SEQ / KVTOK; kt++) {
        CP_WAIT1();
        __syncthreads();
        issue(kt + 2);

        const uint32_t* Ks = usm + (kt % NSTG) * KVSTGW;
        const uint32_t* Vs = Ks + KVTOK * KVPITCH;

        float s[4][4];
        #pragma unroll
        for (int nt = 0; nt < 4; nt++)
            #pragma unroll
            for (int j = 0; j < 4; j++) s[nt][j] = 0.f;
        #pragma unroll
        for (int ks = 0; ks < 8; ks++) {
            #pragma unroll
            for (int nt = 0; nt < 4; nt++) {
                int key = nt * 8 + g;
                int d0 = ks * 8 + tg;
                int sw = ((key >> 2) & 1) << 2;
                uint32_t b0 = Ks[key * KVPITCH + (d0 ^ sw)];
                uint32_t b1 = Ks[key * KVPITCH + ((d0 + 4) ^ sw)];
                mma_tf32(s[nt], aq[ks], b0, b1);
            }
        }

        float tl = -1e30f, th = -1e30f;
        #pragma unroll
        for (int nt = 0; nt < 4; nt++) {
            tl = fmaxf(tl, fmaxf(s[nt][0], s[nt][1]));
            th = fmaxf(th, fmaxf(s[nt][2], s[nt][3]));
        }
        tl = fmaxf(tl, __shfl_xor_sync(0xffffffffu, tl, 1));
        tl = fmaxf(tl, __shfl_xor_sync(0xffffffffu, tl, 2));
        th = fmaxf(th, __shfl_xor_sync(0xffffffffu, th, 1));
        th = fmaxf(th, __shfl_xor_sync(0xffffffffu, th, 2));
        float mn_l = fmaxf(m_lo, tl), mn_h = fmaxf(m_hi, th);
        float fl = __expf(m_lo - mn_l), fh = __expf(m_hi - mn_h);
        m_lo = mn_l; m_hi = mn_h;

        float sl = 0.f, sh = 0.f;
        #pragma unroll
        for (int nt = 0; nt < 4; nt++) {
            s[nt][0] = __expf(s[nt][0] - m_lo);
            s[nt][1] = __expf(s[nt][1] - m_lo);
            s[nt][2] = __expf(s[nt][2] - m_hi);
            s[nt][3] = __expf(s[nt][3] - m_hi);
            sl += s[nt][0] + s[nt][1];
            sh += s[nt][2] + s[nt][3];
        }
        sl += __shfl_xor_sync(0xffffffffu, sl, 1);
        sl += __shfl_xor_sync(0xffffffffu, sl, 2);
        sh += __shfl_xor_sync(0xffffffffu, sh, 1);
        sh += __shfl_xor_sync(0xffffffffu, sh, 2);
        l_lo = l_lo * fl + sl;
        l_hi = l_hi * fh + sh;
        #pragma unroll
        for (int nt = 0; nt < 8; nt++) {
            o[nt][0] *= fl; o[nt][1] *= fl;
            o[nt][2] *= fh; o[nt][3] *= fh;
        }

        #pragma unroll
        for (int kk = 0; kk < 4; kk++) {
            float t0 = __shfl_sync(0xffffffffu, s[kk][0], src);
            float t1 = __shfl_sync(0xffffffffu, s[kk][1], src);
            float t2 = __shfl_sync(0xffffffffu, s[kk][2], src);
            float t3 = __shfl_sync(0xffffffffu, s[kk][3], src);
            float u0 = __shfl_sync(0xffffffffu, s[kk][0], src2);
            float u1 = __shfl_sync(0xffffffffu, s[kk][1], src2);
            float u2 = __shfl_sync(0xffffffffu, s[kk][2], src2);
            float u3 = __shfl_sync(0xffffffffu, s[kk][3], src2);
            uint32_t pa[4];
            pa[0] = f2tf(odd ? t1 : t0);
            pa[1] = f2tf(odd ? t3 : t2);
            pa[2] = f2tf(odd ? u1 : u0);
            pa[3] = f2tf(odd ? u3 : u2);
            #pragma unroll
            for (int nt = 0; nt < 8; nt++) {
                int krow = kk * 8 + tg;
                int dd = nt * 8 + g;
                uint32_t b0 = Vs[krow * KVPITCH + dd];
                uint32_t b1 = Vs[(krow + 4) * KVPITCH + dd];
                mma_tf32(o[nt], pa, b0, b1);
            }
        }
    }

    float inv_lo = 1.f / l_lo, inv_hi = 1.f / l_hi;
    #pragma unroll
    for (int nt = 0; nt < 8; nt++) {
        int col = h * DH + nt * 8 + 2 * tg;
        size_t r_lo = (size_t)(b * SEQ + q0 + g) * DM + col;
        size_t r_hi = (size_t)(b * SEQ + q0 + g + 8) * DM + col;
        *(float2*)&O[r_lo] = make_float2(o[nt][0] * inv_lo, o[nt][1] * inv_lo);
        *(float2*)&O[r_hi] = make_float2(o[nt][2] * inv_hi, o[nt][3] * inv_hi);
    }
}

// ---------------- launch ----------------
extern "C" void kernel_launch(void* const* d_in, const int* in_sizes, int n_in,
                              void* d_out, int out_size)
{
    const float* query  = (const float*)d_in[0];
    const float* key_in = (const float*)d_in[1];
    const float* value  = (const float*)d_in[2];
    const float* Wq  = (const float*)d_in[3];
    const float* bq  = (const float*)d_in[4];
    const float* Wk  = (const float*)d_in[5];
    const float* bk  = (const float*)d_in[6];
    const float* Wv  = (const float*)d_in[7];
    const float* bv  = (const float*)d_in[8];
    const float* Wo  = (const float*)d_in[9];
    const float* bo  = (const float*)d_in[10];
    const float* Ws1 = (const float*)d_in[11];
    const float* bs1 = (const float*)d_in[12];
    const float* Ws2 = (const float*)d_in[13];
    const float* bs2 = (const float*)d_in[14];
    const float* Wc1 = (const float*)d_in[15];
    const float* bc1 = (const float*)d_in[16];
    const float* Wc2 = (const float*)d_in[17];
    const float* bc2 = (const float*)d_in[18];

    float *pQ, *pK, *pVV, *pVC, *pH, *pVD, *pAO, *pCW, *pWT, *pPART, *pWVB;
    cudaGetSymbolAddress((void**)&pQ,    g_Q);
    cudaGetSymbolAddress((void**)&pK,    g_K);
    cudaGetSymbolAddress((void**)&pVV,   g_VV);
    cudaGetSymbolAddress((void**)&pVC,   g_VC);
    cudaGetSymbolAddress((void**)&pH,    g_H);
    cudaGetSymbolAddress((void**)&pVD,   g_VD);
    cudaGetSymbolAddress((void**)&pAO,   g_AO);
    cudaGetSymbolAddress((void**)&pCW,   g_CW);
    cudaGetSymbolAddress((void**)&pWT,   g_WT);
    cudaGetSymbolAddress((void**)&pPART, g_PART);
    cudaGetSymbolAddress((void**)&pWVB,  g_WVB);

    cudaFuncSetAttribute(proj4,            cudaFuncAttributeMaxDynamicSharedMemorySize, SMEM_GEMM);
    cudaFuncSetAttribute((tgemm<2,false>), cudaFuncAttributeMaxDynamicSharedMemorySize, SMEM_GEMM);
    cudaFuncSetAttribute((tgemm<3,true>),  cudaFuncAttributeMaxDynamicSharedMemorySize, SMEM_GEMM);
    cudaFuncSetAttribute((tgemm<0,false>), cudaFuncAttributeMaxDynamicSharedMemorySize, SMEM_GEMM);
    cudaFuncSetAttribute(attn_kernel,      cudaFuncAttributeMaxDynamicSharedMemorySize, SMEM_ATTN);

    // 0) weights: transpose + tf32 pre-convert
    prep_weights<<<1280, dim3(32, 8)>>>(Wq, Wk, Wv, Wo, Ws1, Ws2, pWT);

    // 1) channel gate: full-BW partial mean, tiny MLP, per-batch scaled Wv
    mean_part_kernel<<<dim3(8, Bn), 256>>>(value, pPART);
    gate_kernel<<<Bn, 256>>>(pPART, Wc1, bc1, Wc2, bc2, pCW);
    scale_wv_kernel<<<dim3(DM * DM / 1024, Bn), 256>>>(pWT + WT_V, pCW, pWVB);

    // 2) merged projections Q/K/VV/VC
    proj4<<<dim3(DM / 128, MROWS / 128, 4), 256, SMEM_GEMM>>>(
        query, key_in, value, pWT, pWVB, bq, bk, bv, pQ, pK, pVV, pVC);

    dim3 g512(DM / 128, MROWS / 128);   // (4, 64)
    dim3 g256(HID / 128, MROWS / 128);  // (2, 64)

    // 3) spatial gate hidden = relu(VV @ Ws1 + bs1)
    tgemm<2,false><<<g256, 256, SMEM_GEMM>>>(pVV, pWT + WT_S1, bs1, pH, DM, HID, nullptr, nullptr);

    // 4) v_dual = VV * sigmoid(H @ Ws2 + bs2) + VC  (rounded tf32 for attention)
    tgemm<3,true><<<g512, 256, SMEM_GEMM>>>(pH, pWT + WT_S2, bs2, pVD, HID, DM, pVV, pVC);

    // 5) attention
    attn_kernel<<<dim3(SEQ / 128, NH, Bn), 256, SMEM_ATTN>>>(pQ, pK, pVD, pAO);

    // 6) output projection
    tgemm<0,false><<<g512, 256, SMEM_GEMM>>>(pAO, pWT + WT_O, bo, (float*)d_out, DM, DM, nullptr, nullptr);
}